// round 1
// baseline (speedup 1.0000x reference)
#include <cuda_runtime.h>
#include <math.h>

#define S_LEN 2048
#define BATCH 2
#define EMB   1024
#define NH    16
#define HD    64
#define HID   512
#define MROWS (S_LEN*BATCH)   // 4096

// ---------------- scratch (static device globals; no allocation) ----------
__device__ float g_q  [BATCH*NH*S_LEN*HD];   // (B,H,S,D) 16MB
__device__ float g_k  [BATCH*NH*S_LEN*HD];
__device__ float g_v  [BATCH*NH*S_LEN*HD];
__device__ float g_ctx[MROWS*EMB];           // (S,B,E)   16MB
__device__ float g_t1 [MROWS*HID];           // relu(query@inf1_w.T+b1)
__device__ float g_mcomb[NH*HID];            // head_sig @ inf2_w  (16x512)
__device__ float g_cbias[NH];                // head_sig @ inf2_b
__device__ float g_mask[BATCH*NH*S_LEN];     // (B,H,S) gate in {0,1}

// ---------------- generic NT SGEMM: C = (A @ W^T + bias) * scale ----------
// A: (M,K) row-major, W: (N,K) row-major. M,N multiples of 128, K of 8.
// MODE 0: plain row-major out (N = gridDim.x*128)
// MODE 1: plain + relu
// MODE 2: scatter to (B,H,S,D) layout (m = s*B+b, n = h*D+d)
template<int MODE>
__global__ __launch_bounds__(256)
void sgemm_nt(const float* __restrict__ A, const float* __restrict__ W,
              const float* __restrict__ bias, float* __restrict__ C,
              int K, float scale)
{
    __shared__ float As[8][128];
    __shared__ float Bs[8][128];
    const int tid  = threadIdx.x;
    const int lrow = tid >> 1;          // 0..127
    const int lcol = (tid & 1) * 4;     // 0 or 4
    const int ty   = tid >> 4;          // 0..15 (M dir)
    const int tx   = tid & 15;          // 0..15 (N dir)
    const float* Ab = A + (size_t)blockIdx.y * 128 * K;
    const float* Wb = W + (size_t)blockIdx.x * 128 * K;

    float acc[8][8];
    #pragma unroll
    for (int i = 0; i < 8; i++)
        #pragma unroll
        for (int j = 0; j < 8; j++) acc[i][j] = 0.f;

    for (int k0 = 0; k0 < K; k0 += 8) {
        float4 av = *(const float4*)(Ab + (size_t)lrow * K + k0 + lcol);
        float4 wv = *(const float4*)(Wb + (size_t)lrow * K + k0 + lcol);
        As[lcol+0][lrow] = av.x; As[lcol+1][lrow] = av.y;
        As[lcol+2][lrow] = av.z; As[lcol+3][lrow] = av.w;
        Bs[lcol+0][lrow] = wv.x; Bs[lcol+1][lrow] = wv.y;
        Bs[lcol+2][lrow] = wv.z; Bs[lcol+3][lrow] = wv.w;
        __syncthreads();
        #pragma unroll
        for (int kk = 0; kk < 8; kk++) {
            float4 a0 = *(const float4*)&As[kk][ty*8];
            float4 a1 = *(const float4*)&As[kk][ty*8+4];
            float4 b0 = *(const float4*)&Bs[kk][tx*8];
            float4 b1 = *(const float4*)&Bs[kk][tx*8+4];
            float ra[8] = {a0.x,a0.y,a0.z,a0.w,a1.x,a1.y,a1.z,a1.w};
            float rb[8] = {b0.x,b0.y,b0.z,b0.w,b1.x,b1.y,b1.z,b1.w};
            #pragma unroll
            for (int i = 0; i < 8; i++)
                #pragma unroll
                for (int j = 0; j < 8; j++)
                    acc[i][j] += ra[i] * rb[j];
        }
        __syncthreads();
    }

    #pragma unroll
    for (int i = 0; i < 8; i++) {
        const int m = blockIdx.y * 128 + ty * 8 + i;
        #pragma unroll
        for (int j = 0; j < 8; j++) {
            const int n = blockIdx.x * 128 + tx * 8 + j;
            float v = (acc[i][j] + bias[n]) * scale;
            if (MODE == 1) v = fmaxf(v, 0.f);
            if (MODE == 2) {
                const int s = m >> 1, b = m & 1;       // BATCH == 2
                const int h = n >> 6, d = n & 63;      // HD == 64
                C[(((size_t)(b * NH + h)) * S_LEN + s) * HD + d] = v;
            } else {
                C[(size_t)m * (gridDim.x * 128) + n] = v;
            }
        }
    }
}

// ---------------- fold head_sig into inf2: mcomb = hs @ w2, cbias = hs @ b2
__global__ void combine_sig(const float* __restrict__ hs,
                            const float* __restrict__ w2,
                            const float* __restrict__ b2,
                            float* __restrict__ mcomb,
                            float* __restrict__ cbias)
{
    const int idx = blockIdx.x * blockDim.x + threadIdx.x;
    if (idx < NH * HID) {
        const int h = idx / HID, k = idx % HID;
        float a = 0.f;
        #pragma unroll
        for (int j = 0; j < 64; j++) a += hs[h*64 + j] * w2[j*HID + k];
        mcomb[idx] = a;
    }
    if (idx < NH) {
        float a = 0.f;
        #pragma unroll
        for (int j = 0; j < 64; j++) a += hs[idx*64 + j] * b2[j];
        cbias[idx] = a;
    }
}

// ---------------- per-row head scores + top-12 threshold mask -------------
// one warp per row m (= s*B + b). scores[h] = t1[m,:] . mcomb[h,:] + cbias[h]
__global__ __launch_bounds__(256)
void head_scores(const float* __restrict__ t1, const float* __restrict__ mcomb,
                 const float* __restrict__ cbias, float* __restrict__ mask)
{
    const int warp = (blockIdx.x * blockDim.x + threadIdx.x) >> 5;
    const int lane = threadIdx.x & 31;
    if (warp >= MROWS) return;
    const float* row = t1 + (size_t)warp * HID;

    float acc[NH];
    #pragma unroll
    for (int h = 0; h < NH; h++) acc[h] = 0.f;
    for (int k = lane; k < HID; k += 32) {
        const float a = row[k];
        #pragma unroll
        for (int h = 0; h < NH; h++) acc[h] += a * mcomb[h*HID + k];
    }
    #pragma unroll
    for (int h = 0; h < NH; h++)
        #pragma unroll
        for (int off = 16; off > 0; off >>= 1)
            acc[h] += __shfl_xor_sync(0xffffffffu, acc[h], off);

    if (lane == 0) {
        float sc[NH], tmp[NH];
        #pragma unroll
        for (int h = 0; h < NH; h++) { sc[h] = acc[h] + cbias[h]; tmp[h] = sc[h]; }
        // 12th-largest (with duplicates) = threshold
        float thr = 0.f;
        for (int it = 0; it < NH - 4; it++) {   // keep = 12
            int bi = 0; float bv = tmp[0];
            #pragma unroll
            for (int h = 1; h < NH; h++) if (tmp[h] > bv) { bv = tmp[h]; bi = h; }
            thr = bv; tmp[bi] = -INFINITY;
        }
        const int s = warp >> 1, b = warp & 1;
        #pragma unroll
        for (int h = 0; h < NH; h++)
            mask[((size_t)(b * NH + h)) * S_LEN + s] = (sc[h] >= thr) ? 1.f : 0.f;
    }
}

// ---------------- flash attention (per (b,h) head, 64-row Q tiles) --------
// Q,K,V: (B,H,S,D) fp32. Output gated by mask and scattered to ctx (S,B,E).
__global__ __launch_bounds__(256)
void flash_attn(const float* __restrict__ Q, const float* __restrict__ K,
                const float* __restrict__ V, const float* __restrict__ gate,
                float* __restrict__ ctx)
{
    extern __shared__ float sm[];
    float* Qs = sm;              // [64][68]  transposed: Qs[d][m]
    float* Ks = Qs + 64*68;      // [64][68]  transposed: Ks[d][n]
    float* Ps = Ks + 64*68;      // [64][68]  Ps[n][m]
    float* Vs = Ps + 64*68;      // [64][68]  Vs[n][d]

    const int tid = threadIdx.x;
    const int bh  = blockIdx.y;
    const int b   = bh >> 4, h = bh & 15;
    const int q0  = blockIdx.x * 64;
    const float* Qg = Q + ((size_t)bh * S_LEN + q0) * HD;
    const float* Kg = K + (size_t)bh * S_LEN * HD;
    const float* Vg = V + (size_t)bh * S_LEN * HD;

    for (int idx = tid; idx < 64*64; idx += 256) {
        const int r = idx >> 6, c = idx & 63;
        Qs[c*68 + r] = Qg[idx];
    }
    const int tr = tid >> 4, tc = tid & 15;
    const int m0 = tr * 4, n0 = tc * 4;

    float mi[4], li[4], Oa[4][4];
    #pragma unroll
    for (int i = 0; i < 4; i++) {
        mi[i] = -INFINITY; li[i] = 0.f;
        #pragma unroll
        for (int j = 0; j < 4; j++) Oa[i][j] = 0.f;
    }
    __syncthreads();

    for (int t = 0; t < S_LEN/64; t++) {
        const float* Kt = Kg + (size_t)t * 64 * HD;
        const float* Vt = Vg + (size_t)t * 64 * HD;
        for (int idx = tid; idx < 64*64; idx += 256) {
            const int r = idx >> 6, c = idx & 63;
            Ks[c*68 + r] = Kt[idx];
            Vs[r*68 + c] = Vt[idx];
        }
        __syncthreads();

        // S = Q K^T (64x64 tile, thread owns 4x4)
        float Sa[4][4];
        #pragma unroll
        for (int i = 0; i < 4; i++)
            #pragma unroll
            for (int j = 0; j < 4; j++) Sa[i][j] = 0.f;
        #pragma unroll 8
        for (int k = 0; k < 64; k++) {
            float4 qv = *(const float4*)(Qs + k*68 + m0);
            float4 kv = *(const float4*)(Ks + k*68 + n0);
            float qa[4] = {qv.x, qv.y, qv.z, qv.w};
            float ka[4] = {kv.x, kv.y, kv.z, kv.w};
            #pragma unroll
            for (int i = 0; i < 4; i++)
                #pragma unroll
                for (int j = 0; j < 4; j++) Sa[i][j] += qa[i] * ka[j];
        }

        // online softmax (row groups of 16 lanes share a row)
        #pragma unroll
        for (int i = 0; i < 4; i++) {
            float rm = fmaxf(fmaxf(Sa[i][0], Sa[i][1]), fmaxf(Sa[i][2], Sa[i][3]));
            rm = fmaxf(rm, __shfl_xor_sync(0xffffffffu, rm, 1));
            rm = fmaxf(rm, __shfl_xor_sync(0xffffffffu, rm, 2));
            rm = fmaxf(rm, __shfl_xor_sync(0xffffffffu, rm, 4));
            rm = fmaxf(rm, __shfl_xor_sync(0xffffffffu, rm, 8));
            const float mnew  = fmaxf(mi[i], rm);
            const float alpha = __expf(mi[i] - mnew);
            mi[i] = mnew;
            float rs = 0.f;
            #pragma unroll
            for (int j = 0; j < 4; j++) {
                const float p = __expf(Sa[i][j] - mnew);
                Ps[(n0 + j)*68 + m0 + i] = p;
                rs += p;
            }
            rs += __shfl_xor_sync(0xffffffffu, rs, 1);
            rs += __shfl_xor_sync(0xffffffffu, rs, 2);
            rs += __shfl_xor_sync(0xffffffffu, rs, 4);
            rs += __shfl_xor_sync(0xffffffffu, rs, 8);
            li[i] = li[i] * alpha + rs;
            #pragma unroll
            for (int j = 0; j < 4; j++) Oa[i][j] *= alpha;
        }
        __syncthreads();

        // O += P V  (thread owns rows m0..m0+3, d cols n0..n0+3)
        #pragma unroll 8
        for (int n = 0; n < 64; n++) {
            float4 pv = *(const float4*)(Ps + n*68 + m0);
            float4 vv = *(const float4*)(Vs + n*68 + n0);
            float pa[4] = {pv.x, pv.y, pv.z, pv.w};
            float va[4] = {vv.x, vv.y, vv.z, vv.w};
            #pragma unroll
            for (int i = 0; i < 4; i++)
                #pragma unroll
                for (int j = 0; j < 4; j++) Oa[i][j] += pa[i] * va[j];
        }
        __syncthreads();
    }

    // epilogue: normalize, gate, scatter to (S,B,E)
    #pragma unroll
    for (int i = 0; i < 4; i++) {
        const int s = q0 + m0 + i;
        const float g   = gate[(size_t)bh * S_LEN + s];
        const float inv = g / li[i];
        float4 o;
        o.x = Oa[i][0] * inv; o.y = Oa[i][1] * inv;
        o.z = Oa[i][2] * inv; o.w = Oa[i][3] * inv;
        *(float4*)(ctx + ((size_t)s * BATCH + b) * EMB + h * HD + n0) = o;
    }
}

// ---------------------------------------------------------------------------
extern "C" void kernel_launch(void* const* d_in, const int* in_sizes, int n_in,
                              void* d_out, int out_size)
{
    const float* query   = (const float*)d_in[0];
    const float* q_w     = (const float*)d_in[1];
    const float* q_b     = (const float*)d_in[2];
    const float* k_w     = (const float*)d_in[3];
    const float* k_b     = (const float*)d_in[4];
    const float* v_w     = (const float*)d_in[5];
    const float* v_b     = (const float*)d_in[6];
    const float* out_w   = (const float*)d_in[7];
    const float* out_b   = (const float*)d_in[8];
    const float* inf1_w  = (const float*)d_in[9];
    const float* inf1_b  = (const float*)d_in[10];
    const float* inf2_w  = (const float*)d_in[11];
    const float* inf2_b  = (const float*)d_in[12];
    const float* head_sig= (const float*)d_in[13];
    float* out = (float*)d_out;

    float *pq, *pk, *pv, *pctx, *pt1, *pmc, *pcb, *pmask;
    cudaGetSymbolAddress((void**)&pq,   g_q);
    cudaGetSymbolAddress((void**)&pk,   g_k);
    cudaGetSymbolAddress((void**)&pv,   g_v);
    cudaGetSymbolAddress((void**)&pctx, g_ctx);
    cudaGetSymbolAddress((void**)&pt1,  g_t1);
    cudaGetSymbolAddress((void**)&pmc,  g_mcomb);
    cudaGetSymbolAddress((void**)&pcb,  g_cbias);
    cudaGetSymbolAddress((void**)&pmask,g_mask);

    // 1) fold head_sig into inf2
    combine_sig<<<(NH*HID + 255)/256, 256>>>(head_sig, inf2_w, inf2_b, pmc, pcb);

    // 2) hidden MLP: t1 = relu(query @ inf1_w.T + b1)   (4096 x 512, K=1024)
    {
        dim3 g(HID/128, MROWS/128);
        sgemm_nt<1><<<g, 256>>>(query, inf1_w, inf1_b, pt1, EMB, 1.f);
    }

    // 3) head scores + top-12 mask (one warp per row)
    head_scores<<<MROWS/8, 256>>>(pt1, pmc, pcb, pmask);

    // 4) Q,K,V projections -> (B,H,S,D). Q scaled by D^-0.5 = 0.125
    {
        dim3 g(EMB/128, MROWS/128);
        sgemm_nt<2><<<g, 256>>>(query, q_w, q_b, pq, EMB, 0.125f);
        sgemm_nt<2><<<g, 256>>>(query, k_w, k_b, pk, EMB, 1.f);
        sgemm_nt<2><<<g, 256>>>(query, v_w, v_b, pv, EMB, 1.f);
    }

    // 5) flash attention + gating -> ctx (S,B,E)
    {
        const int smem = 4 * 64 * 68 * (int)sizeof(float);  // 69632 B
        cudaFuncSetAttribute(flash_attn,
                             cudaFuncAttributeMaxDynamicSharedMemorySize, smem);
        dim3 g(S_LEN/64, BATCH*NH);
        flash_attn<<<g, 256, smem>>>(pq, pk, pv, pmask, pctx);
    }

    // 6) output projection: out = ctx @ out_w.T + out_b
    {
        dim3 g(EMB/128, MROWS/128);
        sgemm_nt<0><<<g, 256>>>(pctx, out_w, out_b, out, EMB, 1.f);
    }
    (void)in_sizes; (void)n_in; (void)out_size;
}

// round 3
// speedup vs baseline: 1.4504x; 1.4504x over previous
#include <cuda_runtime.h>
#include <math.h>
#include <stdint.h>

#define S_LEN 2048
#define BATCH 2
#define EMB   1024
#define NH    16
#define HD    64
#define HID   512
#define MROWS (S_LEN*BATCH)   // 4096

// ---------------- scratch (static device globals; no allocation) ----------
__device__ float g_q  [BATCH*NH*S_LEN*HD];   // (B,H,S,D)
__device__ float g_k  [BATCH*NH*S_LEN*HD];
__device__ float g_v  [BATCH*NH*S_LEN*HD];
__device__ float g_ctx[MROWS*EMB];           // (S,B,E)
__device__ float g_t1 [MROWS*HID];
__device__ float g_mcomb[NH*HID];
__device__ float g_cbias[NH];
__device__ float g_mask[BATCH*NH*S_LEN];

// =================== helpers ===============================================
__device__ __forceinline__ uint32_t f2tf(float x) {
    uint32_t r; asm("cvt.rna.tf32.f32 %0, %1;" : "=r"(r) : "f"(x)); return r;
}
// D += A(16x8,tf32) @ B(8x8,tf32), fp32 accum. row.col layout.
__device__ __forceinline__ void mma_tf32(float* d, const uint32_t* a, const uint32_t* b) {
    asm volatile(
        "mma.sync.aligned.m16n8k8.row.col.f32.tf32.tf32.f32 "
        "{%0,%1,%2,%3}, {%4,%5,%6,%7}, {%8,%9}, {%0,%1,%2,%3};"
        : "+f"(d[0]), "+f"(d[1]), "+f"(d[2]), "+f"(d[3])
        : "r"(a[0]), "r"(a[1]), "r"(a[2]), "r"(a[3]), "r"(b[0]), "r"(b[1]));
}

// =================== tf32 mma.sync NT GEMM =================================
// C(M,N) = (A @ W^T + bias) * scale ; A:(M,K) rm, W:(N,K) rm, K % 32 == 0
// CTA tile 128x128; 8 warps as 2(M)x4(N); warp tile 64x32.
// MODE 0: row-major out; MODE 2: scatter to (B,H,S,D)
template<int MODE>
__global__ __launch_bounds__(256)
void mgemm_tf32(const float* __restrict__ A, const float* __restrict__ W,
                const float* __restrict__ bias, float* __restrict__ C,
                int K, float scale)
{
    __shared__ uint32_t As[128][36];   // [m][k] tf32, pad 36 -> conflict-free frags
    __shared__ uint32_t Ws[128][36];   // [n][k]

    const int tid  = threadIdx.x;
    const int wid  = tid >> 5;
    const int lane = tid & 31;
    const int gid  = lane >> 2;        // 0..7
    const int tig  = lane & 3;         // 0..3
    const int wm   = wid >> 2;         // 0..1 (M dir, 64 rows each)
    const int wn   = wid & 3;          // 0..3 (N dir, 32 cols each)

    const float* Ag = A + (size_t)blockIdx.y * 128 * K;
    const float* Wg = W + (size_t)blockIdx.x * 128 * K;

    float acc[4][4][4];                // [mt][nt][frag]
    #pragma unroll
    for (int i = 0; i < 4; i++)
        #pragma unroll
        for (int j = 0; j < 4; j++)
            #pragma unroll
            for (int f = 0; f < 4; f++) acc[i][j][f] = 0.f;

    const int NC = K >> 5;             // chunks of 32
    float4 ra[4], rb[4];
    // prefetch chunk 0
    #pragma unroll
    for (int i = 0; i < 4; i++) {
        const int fi = tid + i * 256;
        const int row = fi >> 3, col = (fi & 7) * 4;
        ra[i] = *(const float4*)(Ag + (size_t)row * K + col);
        rb[i] = *(const float4*)(Wg + (size_t)row * K + col);
    }

    for (int c = 0; c < NC; c++) {
        __syncthreads();               // previous compute done reading smem
        #pragma unroll
        for (int i = 0; i < 4; i++) {
            const int fi = tid + i * 256;
            const int row = fi >> 3, col = (fi & 7) * 4;
            uint4 va = { f2tf(ra[i].x), f2tf(ra[i].y), f2tf(ra[i].z), f2tf(ra[i].w) };
            uint4 vb = { f2tf(rb[i].x), f2tf(rb[i].y), f2tf(rb[i].z), f2tf(rb[i].w) };
            *(uint4*)&As[row][col] = va;
            *(uint4*)&Ws[row][col] = vb;
        }
        __syncthreads();
        if (c + 1 < NC) {
            const int kn = (c + 1) << 5;
            #pragma unroll
            for (int i = 0; i < 4; i++) {
                const int fi = tid + i * 256;
                const int row = fi >> 3, col = (fi & 7) * 4;
                ra[i] = *(const float4*)(Ag + (size_t)row * K + kn + col);
                rb[i] = *(const float4*)(Wg + (size_t)row * K + kn + col);
            }
        }
        #pragma unroll
        for (int ks = 0; ks < 4; ks++) {
            const int k0 = ks * 8;
            uint32_t af[4][4];
            #pragma unroll
            for (int mt = 0; mt < 4; mt++) {
                const int r = wm * 64 + mt * 16 + gid;
                af[mt][0] = As[r    ][k0 + tig];
                af[mt][1] = As[r + 8][k0 + tig];
                af[mt][2] = As[r    ][k0 + tig + 4];
                af[mt][3] = As[r + 8][k0 + tig + 4];
            }
            uint32_t bf[4][2];
            #pragma unroll
            for (int nt = 0; nt < 4; nt++) {
                const int n = wn * 32 + nt * 8 + gid;
                bf[nt][0] = Ws[n][k0 + tig];
                bf[nt][1] = Ws[n][k0 + tig + 4];
            }
            #pragma unroll
            for (int mt = 0; mt < 4; mt++)
                #pragma unroll
                for (int nt = 0; nt < 4; nt++)
                    mma_tf32(acc[mt][nt], af[mt], bf[nt]);
        }
    }

    // ---- epilogue: fragments -> global ------------------------------------
    #pragma unroll
    for (int mt = 0; mt < 4; mt++) {
        #pragma unroll
        for (int nt = 0; nt < 4; nt++) {
            const int n = blockIdx.x * 128 + wn * 32 + nt * 8 + tig * 2;
            const float b0 = bias[n], b1 = bias[n + 1];
            #pragma unroll
            for (int half = 0; half < 2; half++) {
                const int m = blockIdx.y * 128 + wm * 64 + mt * 16 + gid + half * 8;
                float2 v;
                v.x = (acc[mt][nt][half * 2 + 0] + b0) * scale;
                v.y = (acc[mt][nt][half * 2 + 1] + b1) * scale;
                if (MODE == 2) {
                    const int s = m >> 1, b = m & 1;
                    const int h = n >> 6, d = n & 63;
                    *(float2*)(C + (((size_t)(b * NH + h)) * S_LEN + s) * HD + d) = v;
                } else {
                    *(float2*)(C + (size_t)m * (gridDim.x * 128) + n) = v;
                }
            }
        }
    }
}

// ---------------- fp32 SIMT SGEMM (mask MLP only: exact fp32) -------------
__global__ __launch_bounds__(256)
void sgemm_relu(const float* __restrict__ A, const float* __restrict__ W,
                const float* __restrict__ bias, float* __restrict__ C, int K)
{
    __shared__ float As[8][128];
    __shared__ float Bs[8][128];
    const int tid  = threadIdx.x;
    const int lrow = tid >> 1;
    const int lcol = (tid & 1) * 4;
    const int ty   = tid >> 4;
    const int tx   = tid & 15;
    const float* Ab = A + (size_t)blockIdx.y * 128 * K;
    const float* Wb = W + (size_t)blockIdx.x * 128 * K;

    float acc[8][8];
    #pragma unroll
    for (int i = 0; i < 8; i++)
        #pragma unroll
        for (int j = 0; j < 8; j++) acc[i][j] = 0.f;

    for (int k0 = 0; k0 < K; k0 += 8) {
        float4 av = *(const float4*)(Ab + (size_t)lrow * K + k0 + lcol);
        float4 wv = *(const float4*)(Wb + (size_t)lrow * K + k0 + lcol);
        As[lcol+0][lrow] = av.x; As[lcol+1][lrow] = av.y;
        As[lcol+2][lrow] = av.z; As[lcol+3][lrow] = av.w;
        Bs[lcol+0][lrow] = wv.x; Bs[lcol+1][lrow] = wv.y;
        Bs[lcol+2][lrow] = wv.z; Bs[lcol+3][lrow] = wv.w;
        __syncthreads();
        #pragma unroll
        for (int kk = 0; kk < 8; kk++) {
            float4 a0 = *(const float4*)&As[kk][ty*8];
            float4 a1 = *(const float4*)&As[kk][ty*8+4];
            float4 b0 = *(const float4*)&Bs[kk][tx*8];
            float4 b1 = *(const float4*)&Bs[kk][tx*8+4];
            float rA[8] = {a0.x,a0.y,a0.z,a0.w,a1.x,a1.y,a1.z,a1.w};
            float rB[8] = {b0.x,b0.y,b0.z,b0.w,b1.x,b1.y,b1.z,b1.w};
            #pragma unroll
            for (int i = 0; i < 8; i++)
                #pragma unroll
                for (int j = 0; j < 8; j++)
                    acc[i][j] += rA[i] * rB[j];
        }
        __syncthreads();
    }
    #pragma unroll
    for (int i = 0; i < 8; i++) {
        const int m = blockIdx.y * 128 + ty * 8 + i;
        #pragma unroll
        for (int j = 0; j < 8; j++) {
            const int n = blockIdx.x * 128 + tx * 8 + j;
            C[(size_t)m * (gridDim.x * 128) + n] = fmaxf(acc[i][j] + bias[n], 0.f);
        }
    }
}

// ---------------- fold head_sig into inf2 ---------------------------------
__global__ void combine_sig(const float* __restrict__ hs,
                            const float* __restrict__ w2,
                            const float* __restrict__ b2,
                            float* __restrict__ mcomb,
                            float* __restrict__ cbias)
{
    const int idx = blockIdx.x * blockDim.x + threadIdx.x;
    if (idx < NH * HID) {
        const int h = idx / HID, k = idx % HID;
        float a = 0.f;
        #pragma unroll
        for (int j = 0; j < 64; j++) a += hs[h*64 + j] * w2[j*HID + k];
        mcomb[idx] = a;
    }
    if (idx < NH) {
        float a = 0.f;
        #pragma unroll
        for (int j = 0; j < 64; j++) a += hs[idx*64 + j] * b2[j];
        cbias[idx] = a;
    }
}

// ---------------- per-row head scores + top-12 threshold mask -------------
__global__ __launch_bounds__(256)
void head_scores(const float* __restrict__ t1, const float* __restrict__ mcomb,
                 const float* __restrict__ cbias, float* __restrict__ mask)
{
    const int warp = (blockIdx.x * blockDim.x + threadIdx.x) >> 5;
    const int lane = threadIdx.x & 31;
    if (warp >= MROWS) return;
    const float* row = t1 + (size_t)warp * HID;

    float acc[NH];
    #pragma unroll
    for (int h = 0; h < NH; h++) acc[h] = 0.f;
    for (int k = lane; k < HID; k += 32) {
        const float a = row[k];
        #pragma unroll
        for (int h = 0; h < NH; h++) acc[h] += a * mcomb[h*HID + k];
    }
    #pragma unroll
    for (int h = 0; h < NH; h++)
        #pragma unroll
        for (int off = 16; off > 0; off >>= 1)
            acc[h] += __shfl_xor_sync(0xffffffffu, acc[h], off);

    if (lane == 0) {
        float sc[NH], tmp[NH];
        #pragma unroll
        for (int h = 0; h < NH; h++) { sc[h] = acc[h] + cbias[h]; tmp[h] = sc[h]; }
        float thr = 0.f;
        for (int it = 0; it < NH - 4; it++) {
            int bi = 0; float bv = tmp[0];
            #pragma unroll
            for (int h = 1; h < NH; h++) if (tmp[h] > bv) { bv = tmp[h]; bi = h; }
            thr = bv; tmp[bi] = -INFINITY;
        }
        const int s = warp >> 1, b = warp & 1;
        #pragma unroll
        for (int h = 0; h < NH; h++)
            mask[((size_t)(b * NH + h)) * S_LEN + s] = (sc[h] >= thr) ? 1.f : 0.f;
    }
}

// ---------------- flash attention (fp32 SIMT) ------------------------------
__global__ __launch_bounds__(256)
void flash_attn(const float* __restrict__ Q, const float* __restrict__ K,
                const float* __restrict__ V, const float* __restrict__ gate,
                float* __restrict__ ctx)
{
    extern __shared__ float smf[];
    float* Qs = smf;
    float* Ks = Qs + 64*68;
    float* Ps = Ks + 64*68;
    float* Vs = Ps + 64*68;

    const int tid = threadIdx.x;
    const int bh  = blockIdx.y;
    const int b   = bh >> 4, h = bh & 15;
    const int q0  = blockIdx.x * 64;
    const float* Qg = Q + ((size_t)bh * S_LEN + q0) * HD;
    const float* Kg = K + (size_t)bh * S_LEN * HD;
    const float* Vg = V + (size_t)bh * S_LEN * HD;

    for (int idx = tid; idx < 64*64; idx += 256) {
        const int r = idx >> 6, c = idx & 63;
        Qs[c*68 + r] = Qg[idx];
    }
    const int tr = tid >> 4, tc = tid & 15;
    const int m0 = tr * 4, n0 = tc * 4;

    float mi[4], li[4], Oa[4][4];
    #pragma unroll
    for (int i = 0; i < 4; i++) {
        mi[i] = -INFINITY; li[i] = 0.f;
        #pragma unroll
        for (int j = 0; j < 4; j++) Oa[i][j] = 0.f;
    }
    __syncthreads();

    for (int t = 0; t < S_LEN/64; t++) {
        const float* Kt = Kg + (size_t)t * 64 * HD;
        const float* Vt = Vg + (size_t)t * 64 * HD;
        for (int idx = tid; idx < 64*64; idx += 256) {
            const int r = idx >> 6, c = idx & 63;
            Ks[c*68 + r] = Kt[idx];
            Vs[r*68 + c] = Vt[idx];
        }
        __syncthreads();

        float Sa[4][4];
        #pragma unroll
        for (int i = 0; i < 4; i++)
            #pragma unroll
            for (int j = 0; j < 4; j++) Sa[i][j] = 0.f;
        #pragma unroll 8
        for (int k = 0; k < 64; k++) {
            float4 qv = *(const float4*)(Qs + k*68 + m0);
            float4 kv = *(const float4*)(Ks + k*68 + n0);
            float qa[4] = {qv.x, qv.y, qv.z, qv.w};
            float ka[4] = {kv.x, kv.y, kv.z, kv.w};
            #pragma unroll
            for (int i = 0; i < 4; i++)
                #pragma unroll
                for (int j = 0; j < 4; j++) Sa[i][j] += qa[i] * ka[j];
        }

        #pragma unroll
        for (int i = 0; i < 4; i++) {
            float rm = fmaxf(fmaxf(Sa[i][0], Sa[i][1]), fmaxf(Sa[i][2], Sa[i][3]));
            rm = fmaxf(rm, __shfl_xor_sync(0xffffffffu, rm, 1));
            rm = fmaxf(rm, __shfl_xor_sync(0xffffffffu, rm, 2));
            rm = fmaxf(rm, __shfl_xor_sync(0xffffffffu, rm, 4));
            rm = fmaxf(rm, __shfl_xor_sync(0xffffffffu, rm, 8));
            const float mnew  = fmaxf(mi[i], rm);
            const float alpha = __expf(mi[i] - mnew);
            mi[i] = mnew;
            float rs = 0.f;
            #pragma unroll
            for (int j = 0; j < 4; j++) {
                const float p = __expf(Sa[i][j] - mnew);
                Ps[(n0 + j)*68 + m0 + i] = p;
                rs += p;
            }
            rs += __shfl_xor_sync(0xffffffffu, rs, 1);
            rs += __shfl_xor_sync(0xffffffffu, rs, 2);
            rs += __shfl_xor_sync(0xffffffffu, rs, 4);
            rs += __shfl_xor_sync(0xffffffffu, rs, 8);
            li[i] = li[i] * alpha + rs;
            #pragma unroll
            for (int j = 0; j < 4; j++) Oa[i][j] *= alpha;
        }
        __syncthreads();

        #pragma unroll 8
        for (int n = 0; n < 64; n++) {
            float4 pv = *(const float4*)(Ps + n*68 + m0);
            float4 vv = *(const float4*)(Vs + n*68 + n0);
            float pa[4] = {pv.x, pv.y, pv.z, pv.w};
            float va[4] = {vv.x, vv.y, vv.z, vv.w};
            #pragma unroll
            for (int i = 0; i < 4; i++)
                #pragma unroll
                for (int j = 0; j < 4; j++) Oa[i][j] += pa[i] * va[j];
        }
        __syncthreads();
    }

    #pragma unroll
    for (int i = 0; i < 4; i++) {
        const int s = q0 + m0 + i;
        const float g   = gate[(size_t)bh * S_LEN + s];
        const float inv = g / li[i];
        float4 o;
        o.x = Oa[i][0] * inv; o.y = Oa[i][1] * inv;
        o.z = Oa[i][2] * inv; o.w = Oa[i][3] * inv;
        *(float4*)(ctx + ((size_t)s * BATCH + b) * EMB + h * HD + n0) = o;
    }
}

// ---------------------------------------------------------------------------
extern "C" void kernel_launch(void* const* d_in, const int* in_sizes, int n_in,
                              void* d_out, int out_size)
{
    const float* query   = (const float*)d_in[0];
    const float* q_w     = (const float*)d_in[1];
    const float* q_b     = (const float*)d_in[2];
    const float* k_w     = (const float*)d_in[3];
    const float* k_b     = (const float*)d_in[4];
    const float* v_w     = (const float*)d_in[5];
    const float* v_b     = (const float*)d_in[6];
    const float* out_w   = (const float*)d_in[7];
    const float* out_b   = (const float*)d_in[8];
    const float* inf1_w  = (const float*)d_in[9];
    const float* inf1_b  = (const float*)d_in[10];
    const float* inf2_w  = (const float*)d_in[11];
    const float* inf2_b  = (const float*)d_in[12];
    const float* head_sig= (const float*)d_in[13];
    float* out = (float*)d_out;

    float *pq, *pk, *pv, *pctx, *pt1, *pmc, *pcb, *pmask;
    cudaGetSymbolAddress((void**)&pq,   g_q);
    cudaGetSymbolAddress((void**)&pk,   g_k);
    cudaGetSymbolAddress((void**)&pv,   g_v);
    cudaGetSymbolAddress((void**)&pctx, g_ctx);
    cudaGetSymbolAddress((void**)&pt1,  g_t1);
    cudaGetSymbolAddress((void**)&pmc,  g_mcomb);
    cudaGetSymbolAddress((void**)&pcb,  g_cbias);
    cudaGetSymbolAddress((void**)&pmask,g_mask);

    // 1) fold head_sig into inf2
    combine_sig<<<(NH*HID + 255)/256, 256>>>(head_sig, inf2_w, inf2_b, pmc, pcb);

    // 2) mask MLP (exact fp32 for top-k stability)
    {
        dim3 g(HID/128, MROWS/128);
        sgemm_relu<<<g, 256>>>(query, inf1_w, inf1_b, pt1, EMB);
    }

    // 3) head scores + top-12 mask
    head_scores<<<MROWS/8, 256>>>(pt1, pmc, pcb, pmask);

    // 4) Q,K,V projections (tf32 mma.sync) -> (B,H,S,D). Q scaled by 0.125
    {
        dim3 g(EMB/128, MROWS/128);
        mgemm_tf32<2><<<g, 256>>>(query, q_w, q_b, pq, EMB, 0.125f);
        mgemm_tf32<2><<<g, 256>>>(query, k_w, k_b, pk, EMB, 1.f);
        mgemm_tf32<2><<<g, 256>>>(query, v_w, v_b, pv, EMB, 1.f);
    }

    // 5) flash attention + gating -> ctx (S,B,E)
    {
        const int smem = 4 * 64 * 68 * (int)sizeof(float);
        cudaFuncSetAttribute(flash_attn,
                             cudaFuncAttributeMaxDynamicSharedMemorySize, smem);
        dim3 g(S_LEN/64, BATCH*NH);
        flash_attn<<<g, 256, smem>>>(pq, pk, pv, pmask, pctx);
    }

    // 6) output projection (tf32 mma.sync)
    {
        dim3 g(EMB/128, MROWS/128);
        mgemm_tf32<0><<<g, 256>>>(pctx, out_w, out_b, out, EMB, 1.f);
    }
    (void)in_sizes; (void)n_in; (void)out_size;
}

// round 4
// speedup vs baseline: 2.7775x; 1.9149x over previous
#include <cuda_runtime.h>
#include <math.h>
#include <stdint.h>

#define S_LEN 2048
#define BATCH 2
#define EMB   1024
#define NH    16
#define HD    64
#define HID   512
#define MROWS (S_LEN*BATCH)   // 4096

// ---------------- scratch (static device globals; no allocation) ----------
__device__ float g_q  [BATCH*NH*S_LEN*HD];   // (B,H,S,D)
__device__ float g_k  [BATCH*NH*S_LEN*HD];
__device__ float g_v  [BATCH*NH*S_LEN*HD];
__device__ float g_ctx[MROWS*EMB];           // (S,B,E)
__device__ float g_t1 [MROWS*HID];
__device__ float g_mcomb[NH*HID];
__device__ float g_cbias[NH];
__device__ float g_mask[BATCH*NH*S_LEN];

// =================== helpers ===============================================
__device__ __forceinline__ uint32_t f2tf(float x) {
    uint32_t r; asm("cvt.rna.tf32.f32 %0, %1;" : "=r"(r) : "f"(x)); return r;
}
__device__ __forceinline__ uint32_t smem_u32(const void* p) {
    uint32_t a;
    asm("{ .reg .u64 t; cvta.to.shared.u64 t, %1; cvt.u32.u64 %0, t; }"
        : "=r"(a) : "l"(p));
    return a;
}
__device__ __forceinline__ void cp16(uint32_t saddr, const void* g) {
    asm volatile("cp.async.cg.shared.global [%0], [%1], 16;"
                 :: "r"(saddr), "l"(g) : "memory");
}
// D += A(16x8,tf32) @ B(8x8,tf32)^T-layout, fp32 accum. row.col.
__device__ __forceinline__ void mma_tf32(float* d, const uint32_t* a, const uint32_t* b) {
    asm volatile(
        "mma.sync.aligned.m16n8k8.row.col.f32.tf32.tf32.f32 "
        "{%0,%1,%2,%3}, {%4,%5,%6,%7}, {%8,%9}, {%0,%1,%2,%3};"
        : "+f"(d[0]), "+f"(d[1]), "+f"(d[2]), "+f"(d[3])
        : "r"(a[0]), "r"(a[1]), "r"(a[2]), "r"(a[3]), "r"(b[0]), "r"(b[1]));
}

// =================== tf32 mma.sync NT GEMM (from R3, unchanged) ============
template<int MODE>
__global__ __launch_bounds__(256)
void mgemm_tf32(const float* __restrict__ A, const float* __restrict__ W,
                const float* __restrict__ bias, float* __restrict__ C,
                int K, float scale)
{
    __shared__ uint32_t As[128][36];
    __shared__ uint32_t Ws[128][36];

    const int tid  = threadIdx.x;
    const int wid  = tid >> 5;
    const int lane = tid & 31;
    const int gid  = lane >> 2;
    const int tig  = lane & 3;
    const int wm   = wid >> 2;
    const int wn   = wid & 3;

    const float* Ag = A + (size_t)blockIdx.y * 128 * K;
    const float* Wg = W + (size_t)blockIdx.x * 128 * K;

    float acc[4][4][4];
    #pragma unroll
    for (int i = 0; i < 4; i++)
        #pragma unroll
        for (int j = 0; j < 4; j++)
            #pragma unroll
            for (int f = 0; f < 4; f++) acc[i][j][f] = 0.f;

    const int NC = K >> 5;
    float4 ra[4], rb[4];
    #pragma unroll
    for (int i = 0; i < 4; i++) {
        const int fi = tid + i * 256;
        const int row = fi >> 3, col = (fi & 7) * 4;
        ra[i] = *(const float4*)(Ag + (size_t)row * K + col);
        rb[i] = *(const float4*)(Wg + (size_t)row * K + col);
    }

    for (int c = 0; c < NC; c++) {
        __syncthreads();
        #pragma unroll
        for (int i = 0; i < 4; i++) {
            const int fi = tid + i * 256;
            const int row = fi >> 3, col = (fi & 7) * 4;
            uint4 va = { f2tf(ra[i].x), f2tf(ra[i].y), f2tf(ra[i].z), f2tf(ra[i].w) };
            uint4 vb = { f2tf(rb[i].x), f2tf(rb[i].y), f2tf(rb[i].z), f2tf(rb[i].w) };
            *(uint4*)&As[row][col] = va;
            *(uint4*)&Ws[row][col] = vb;
        }
        __syncthreads();
        if (c + 1 < NC) {
            const int kn = (c + 1) << 5;
            #pragma unroll
            for (int i = 0; i < 4; i++) {
                const int fi = tid + i * 256;
                const int row = fi >> 3, col = (fi & 7) * 4;
                ra[i] = *(const float4*)(Ag + (size_t)row * K + kn + col);
                rb[i] = *(const float4*)(Wg + (size_t)row * K + kn + col);
            }
        }
        #pragma unroll
        for (int ks = 0; ks < 4; ks++) {
            const int k0 = ks * 8;
            uint32_t af[4][4];
            #pragma unroll
            for (int mt = 0; mt < 4; mt++) {
                const int r = wm * 64 + mt * 16 + gid;
                af[mt][0] = As[r    ][k0 + tig];
                af[mt][1] = As[r + 8][k0 + tig];
                af[mt][2] = As[r    ][k0 + tig + 4];
                af[mt][3] = As[r + 8][k0 + tig + 4];
            }
            uint32_t bf[4][2];
            #pragma unroll
            for (int nt = 0; nt < 4; nt++) {
                const int n = wn * 32 + nt * 8 + gid;
                bf[nt][0] = Ws[n][k0 + tig];
                bf[nt][1] = Ws[n][k0 + tig + 4];
            }
            #pragma unroll
            for (int mt = 0; mt < 4; mt++)
                #pragma unroll
                for (int nt = 0; nt < 4; nt++)
                    mma_tf32(acc[mt][nt], af[mt], bf[nt]);
        }
    }

    #pragma unroll
    for (int mt = 0; mt < 4; mt++) {
        #pragma unroll
        for (int nt = 0; nt < 4; nt++) {
            const int n = blockIdx.x * 128 + wn * 32 + nt * 8 + tig * 2;
            const float b0 = bias[n], b1 = bias[n + 1];
            #pragma unroll
            for (int half = 0; half < 2; half++) {
                const int m = blockIdx.y * 128 + wm * 64 + mt * 16 + gid + half * 8;
                float2 v;
                v.x = (acc[mt][nt][half * 2 + 0] + b0) * scale;
                v.y = (acc[mt][nt][half * 2 + 1] + b1) * scale;
                if (MODE == 2) {
                    const int s = m >> 1, b = m & 1;
                    const int h = n >> 6, d = n & 63;
                    *(float2*)(C + (((size_t)(b * NH + h)) * S_LEN + s) * HD + d) = v;
                } else {
                    *(float2*)(C + (size_t)m * (gridDim.x * 128) + n) = v;
                }
            }
        }
    }
}

// =================== tensor-core flash attention ===========================
// grid (S_LEN/128, B*NH), 256 threads. Warp w owns Q rows [w*16, w*16+16).
// K/V tiles of 64 keys, double-buffered via cp.async.
// smem (words): buf0K @0, buf0V @4352, buf1K @8704, buf1V @13056  (69632 B)
__global__ __launch_bounds__(256, 2)
void flash_tc(const float* __restrict__ Q, const float* __restrict__ Kg,
              const float* __restrict__ Vg, const float* __restrict__ gate,
              float* __restrict__ ctx)
{
    extern __shared__ uint32_t sw[];
    const uint32_t sbase = smem_u32(sw);
    const int tid  = threadIdx.x;
    const int wid  = tid >> 5;
    const int lane = tid & 31;
    const int gid  = lane >> 2;
    const int tig  = lane & 3;
    const int bh   = blockIdx.y;
    const int b    = bh >> 4, h = bh & 15;
    const int q0   = blockIdx.x * 128;

    const float* Qt = Q  + ((size_t)bh * S_LEN + q0) * HD;
    const float* Kb = Kg + (size_t)bh * S_LEN * HD;
    const float* Vb = Vg + (size_t)bh * S_LEN * HD;

    // ---- stage Q (tf32) then load Q fragments into registers --------------
    #pragma unroll
    for (int i = 0; i < 8; i++) {
        const int fi = tid + i * 256;            // 0..2047
        const int r = fi >> 4, c4 = (fi & 15) * 4;
        float4 v = *(const float4*)(Qt + r * 64 + c4);
        uint32_t* d = &sw[r * 68 + c4];
        d[0] = f2tf(v.x); d[1] = f2tf(v.y); d[2] = f2tf(v.z); d[3] = f2tf(v.w);
    }
    __syncthreads();
    uint32_t qa[8][4];
    {
        const int r0 = wid * 16 + gid;
        #pragma unroll
        for (int ks = 0; ks < 8; ks++) {
            qa[ks][0] = sw[ r0      * 68 + ks * 8 + tig    ];
            qa[ks][1] = sw[(r0 + 8) * 68 + ks * 8 + tig    ];
            qa[ks][2] = sw[ r0      * 68 + ks * 8 + tig + 4];
            qa[ks][3] = sw[(r0 + 8) * 68 + ks * 8 + tig + 4];
        }
    }
    __syncthreads();

    // ---- issue first two K/V tiles -----------------------------------------
    #pragma unroll 1
    for (int t = 0; t < 2; t++) {
        const uint32_t kb = sbase + (t ? 8704u : 0u) * 4u;
        const uint32_t vb = kb + 4352u * 4u;
        const float* Ksrc = Kb + (size_t)t * 64 * 64;
        const float* Vsrc = Vb + (size_t)t * 64 * 64;
        #pragma unroll
        for (int i = 0; i < 4; i++) {
            const int fi = tid + i * 256;        // 0..1023
            const int r = fi >> 4, c4 = (fi & 15) * 4;
            cp16(kb + (uint32_t)(r * 68 + c4) * 4u, Ksrc + r * 64 + c4);
            cp16(vb + (uint32_t)(r * 68 + c4) * 4u, Vsrc + r * 64 + c4);
        }
        asm volatile("cp.async.commit_group;" ::: "memory");
    }

    float miA = -INFINITY, miB = -INFINITY, liA = 0.f, liB = 0.f;
    float oa[8][4];
    #pragma unroll
    for (int nt = 0; nt < 8; nt++)
        #pragma unroll
        for (int f = 0; f < 4; f++) oa[nt][f] = 0.f;

    const int NT = S_LEN / 64;                   // 32
    for (int t = 0; t < NT; t++) {
        if (t < NT - 2) asm volatile("cp.async.wait_group 1;" ::: "memory");
        else            asm volatile("cp.async.wait_group 0;" ::: "memory");
        __syncthreads();
        const uint32_t* Ks = sw + ((t & 1) ? 8704 : 0);
        const uint32_t* Vs = Ks + 4352;

        // ---- S = Q K^T (warp tile 16x64) -----------------------------------
        float sa[8][4];
        #pragma unroll
        for (int nt = 0; nt < 8; nt++)
            #pragma unroll
            for (int f = 0; f < 4; f++) sa[nt][f] = 0.f;
        #pragma unroll
        for (int ks = 0; ks < 8; ks++) {
            #pragma unroll
            for (int nt = 0; nt < 8; nt++) {
                uint32_t bf[2];
                bf[0] = Ks[(nt * 8 + gid) * 68 + ks * 8 + tig    ];
                bf[1] = Ks[(nt * 8 + gid) * 68 + ks * 8 + tig + 4];
                mma_tf32(sa[nt], qa[ks], bf);
            }
        }

        // ---- online softmax (rows gid and gid+8, quad reductions) ----------
        float rmA = -INFINITY, rmB = -INFINITY;
        #pragma unroll
        for (int nt = 0; nt < 8; nt++) {
            rmA = fmaxf(rmA, fmaxf(sa[nt][0], sa[nt][1]));
            rmB = fmaxf(rmB, fmaxf(sa[nt][2], sa[nt][3]));
        }
        rmA = fmaxf(rmA, __shfl_xor_sync(0xffffffffu, rmA, 1));
        rmA = fmaxf(rmA, __shfl_xor_sync(0xffffffffu, rmA, 2));
        rmB = fmaxf(rmB, __shfl_xor_sync(0xffffffffu, rmB, 1));
        rmB = fmaxf(rmB, __shfl_xor_sync(0xffffffffu, rmB, 2));

        const float mAn = fmaxf(miA, rmA);
        const float mBn = fmaxf(miB, rmB);
        const float aA  = __expf(miA - mAn);
        const float aB  = __expf(miB - mBn);
        miA = mAn; miB = mBn;

        float rsA = 0.f, rsB = 0.f;
        uint32_t pu[8][4];
        #pragma unroll
        for (int nt = 0; nt < 8; nt++) {
            const float p0 = __expf(sa[nt][0] - mAn);
            const float p1 = __expf(sa[nt][1] - mAn);
            const float p2 = __expf(sa[nt][2] - mBn);
            const float p3 = __expf(sa[nt][3] - mBn);
            rsA += p0 + p1; rsB += p2 + p3;
            pu[nt][0] = f2tf(p0); pu[nt][1] = f2tf(p1);
            pu[nt][2] = f2tf(p2); pu[nt][3] = f2tf(p3);
        }
        rsA += __shfl_xor_sync(0xffffffffu, rsA, 1);
        rsA += __shfl_xor_sync(0xffffffffu, rsA, 2);
        rsB += __shfl_xor_sync(0xffffffffu, rsB, 1);
        rsB += __shfl_xor_sync(0xffffffffu, rsB, 2);
        liA = liA * aA + rsA;
        liB = liB * aB + rsB;
        #pragma unroll
        for (int nt = 0; nt < 8; nt++) {
            oa[nt][0] *= aA; oa[nt][1] *= aA;
            oa[nt][2] *= aB; oa[nt][3] *= aB;
        }

        // ---- O += P V (P remapped to A-fragments via quad shfl) ------------
        const int srcA = (lane & ~3) | (tig >> 1);
        const int srcB = srcA + 2;
        #pragma unroll
        for (int ks = 0; ks < 8; ks++) {
            const uint32_t v00 = __shfl_sync(0xffffffffu, pu[ks][0], srcA);
            const uint32_t v01 = __shfl_sync(0xffffffffu, pu[ks][1], srcA);
            const uint32_t v10 = __shfl_sync(0xffffffffu, pu[ks][2], srcA);
            const uint32_t v11 = __shfl_sync(0xffffffffu, pu[ks][3], srcA);
            const uint32_t v20 = __shfl_sync(0xffffffffu, pu[ks][0], srcB);
            const uint32_t v21 = __shfl_sync(0xffffffffu, pu[ks][1], srcB);
            const uint32_t v30 = __shfl_sync(0xffffffffu, pu[ks][2], srcB);
            const uint32_t v31 = __shfl_sync(0xffffffffu, pu[ks][3], srcB);
            uint32_t af[4];
            af[0] = (tig & 1) ? v01 : v00;
            af[1] = (tig & 1) ? v11 : v10;
            af[2] = (tig & 1) ? v21 : v20;
            af[3] = (tig & 1) ? v31 : v30;
            #pragma unroll
            for (int nt = 0; nt < 8; nt++) {
                uint32_t bf[2];
                bf[0] = Vs[(ks * 8 + tig    ) * 68 + nt * 8 + gid];
                bf[1] = Vs[(ks * 8 + tig + 4) * 68 + nt * 8 + gid];
                mma_tf32(oa[nt], af, bf);
            }
        }
        __syncthreads();

        // ---- prefetch tile t+2 into the buffer just freed -------------------
        if (t + 2 < NT) {
            const uint32_t kb = sbase + ((t & 1) ? 8704u : 0u) * 4u;
            const uint32_t vb = kb + 4352u * 4u;
            const float* Ksrc = Kb + (size_t)(t + 2) * 64 * 64;
            const float* Vsrc = Vb + (size_t)(t + 2) * 64 * 64;
            #pragma unroll
            for (int i = 0; i < 4; i++) {
                const int fi = tid + i * 256;
                const int r = fi >> 4, c4 = (fi & 15) * 4;
                cp16(kb + (uint32_t)(r * 68 + c4) * 4u, Ksrc + r * 64 + c4);
                cp16(vb + (uint32_t)(r * 68 + c4) * 4u, Vsrc + r * 64 + c4);
            }
            asm volatile("cp.async.commit_group;" ::: "memory");
        }
    }

    // ---- epilogue: normalize, gate, scatter to ctx (S,B,E) -----------------
    const int sA = q0 + wid * 16 + gid;
    const int sB = sA + 8;
    const float gA = gate[(size_t)bh * S_LEN + sA];
    const float gB = gate[(size_t)bh * S_LEN + sB];
    const float invA = gA / liA;
    const float invB = gB / liB;
    #pragma unroll
    for (int nt = 0; nt < 8; nt++) {
        const int col = h * 64 + nt * 8 + tig * 2;
        float2 va = { oa[nt][0] * invA, oa[nt][1] * invA };
        float2 vb = { oa[nt][2] * invB, oa[nt][3] * invB };
        *(float2*)(ctx + ((size_t)sA * BATCH + b) * EMB + col) = va;
        *(float2*)(ctx + ((size_t)sB * BATCH + b) * EMB + col) = vb;
    }
}

// ---------------- fp32 SIMT SGEMM (mask MLP only: exact fp32) -------------
__global__ __launch_bounds__(256)
void sgemm_relu(const float* __restrict__ A, const float* __restrict__ W,
                const float* __restrict__ bias, float* __restrict__ C, int K)
{
    __shared__ float As[8][128];
    __shared__ float Bs[8][128];
    const int tid  = threadIdx.x;
    const int lrow = tid >> 1;
    const int lcol = (tid & 1) * 4;
    const int ty   = tid >> 4;
    const int tx   = tid & 15;
    const float* Ab = A + (size_t)blockIdx.y * 128 * K;
    const float* Wb = W + (size_t)blockIdx.x * 128 * K;

    float acc[8][8];
    #pragma unroll
    for (int i = 0; i < 8; i++)
        #pragma unroll
        for (int j = 0; j < 8; j++) acc[i][j] = 0.f;

    for (int k0 = 0; k0 < K; k0 += 8) {
        float4 av = *(const float4*)(Ab + (size_t)lrow * K + k0 + lcol);
        float4 wv = *(const float4*)(Wb + (size_t)lrow * K + k0 + lcol);
        As[lcol+0][lrow] = av.x; As[lcol+1][lrow] = av.y;
        As[lcol+2][lrow] = av.z; As[lcol+3][lrow] = av.w;
        Bs[lcol+0][lrow] = wv.x; Bs[lcol+1][lrow] = wv.y;
        Bs[lcol+2][lrow] = wv.z; Bs[lcol+3][lrow] = wv.w;
        __syncthreads();
        #pragma unroll
        for (int kk = 0; kk < 8; kk++) {
            float4 a0 = *(const float4*)&As[kk][ty*8];
            float4 a1 = *(const float4*)&As[kk][ty*8+4];
            float4 b0 = *(const float4*)&Bs[kk][tx*8];
            float4 b1 = *(const float4*)&Bs[kk][tx*8+4];
            float rA[8] = {a0.x,a0.y,a0.z,a0.w,a1.x,a1.y,a1.z,a1.w};
            float rB[8] = {b0.x,b0.y,b0.z,b0.w,b1.x,b1.y,b1.z,b1.w};
            #pragma unroll
            for (int i = 0; i < 8; i++)
                #pragma unroll
                for (int j = 0; j < 8; j++)
                    acc[i][j] += rA[i] * rB[j];
        }
        __syncthreads();
    }
    #pragma unroll
    for (int i = 0; i < 8; i++) {
        const int m = blockIdx.y * 128 + ty * 8 + i;
        #pragma unroll
        for (int j = 0; j < 8; j++) {
            const int n = blockIdx.x * 128 + tx * 8 + j;
            C[(size_t)m * (gridDim.x * 128) + n] = fmaxf(acc[i][j] + bias[n], 0.f);
        }
    }
}

// ---------------- fold head_sig into inf2 ---------------------------------
__global__ void combine_sig(const float* __restrict__ hs,
                            const float* __restrict__ w2,
                            const float* __restrict__ b2,
                            float* __restrict__ mcomb,
                            float* __restrict__ cbias)
{
    const int idx = blockIdx.x * blockDim.x + threadIdx.x;
    if (idx < NH * HID) {
        const int h = idx / HID, k = idx % HID;
        float a = 0.f;
        #pragma unroll
        for (int j = 0; j < 64; j++) a += hs[h*64 + j] * w2[j*HID + k];
        mcomb[idx] = a;
    }
    if (idx < NH) {
        float a = 0.f;
        #pragma unroll
        for (int j = 0; j < 64; j++) a += hs[idx*64 + j] * b2[j];
        cbias[idx] = a;
    }
}

// ---------------- per-row head scores + top-12 threshold mask -------------
__global__ __launch_bounds__(256)
void head_scores(const float* __restrict__ t1, const float* __restrict__ mcomb,
                 const float* __restrict__ cbias, float* __restrict__ mask)
{
    const int warp = (blockIdx.x * blockDim.x + threadIdx.x) >> 5;
    const int lane = threadIdx.x & 31;
    if (warp >= MROWS) return;
    const float* row = t1 + (size_t)warp * HID;

    float acc[NH];
    #pragma unroll
    for (int h = 0; h < NH; h++) acc[h] = 0.f;
    for (int k = lane; k < HID; k += 32) {
        const float a = row[k];
        #pragma unroll
        for (int h = 0; h < NH; h++) acc[h] += a * mcomb[h*HID + k];
    }
    #pragma unroll
    for (int h = 0; h < NH; h++)
        #pragma unroll
        for (int off = 16; off > 0; off >>= 1)
            acc[h] += __shfl_xor_sync(0xffffffffu, acc[h], off);

    if (lane == 0) {
        float sc[NH], tmp[NH];
        #pragma unroll
        for (int h = 0; h < NH; h++) { sc[h] = acc[h] + cbias[h]; tmp[h] = sc[h]; }
        float thr = 0.f;
        for (int it = 0; it < NH - 4; it++) {
            int bi = 0; float bv = tmp[0];
            #pragma unroll
            for (int h = 1; h < NH; h++) if (tmp[h] > bv) { bv = tmp[h]; bi = h; }
            thr = bv; tmp[bi] = -INFINITY;
        }
        const int s = warp >> 1, b = warp & 1;
        #pragma unroll
        for (int h = 0; h < NH; h++)
            mask[((size_t)(b * NH + h)) * S_LEN + s] = (sc[h] >= thr) ? 1.f : 0.f;
    }
}

// ---------------------------------------------------------------------------
extern "C" void kernel_launch(void* const* d_in, const int* in_sizes, int n_in,
                              void* d_out, int out_size)
{
    const float* query   = (const float*)d_in[0];
    const float* q_w     = (const float*)d_in[1];
    const float* q_b     = (const float*)d_in[2];
    const float* k_w     = (const float*)d_in[3];
    const float* k_b     = (const float*)d_in[4];
    const float* v_w     = (const float*)d_in[5];
    const float* v_b     = (const float*)d_in[6];
    const float* out_w   = (const float*)d_in[7];
    const float* out_b   = (const float*)d_in[8];
    const float* inf1_w  = (const float*)d_in[9];
    const float* inf1_b  = (const float*)d_in[10];
    const float* inf2_w  = (const float*)d_in[11];
    const float* inf2_b  = (const float*)d_in[12];
    const float* head_sig= (const float*)d_in[13];
    float* out = (float*)d_out;

    float *pq, *pk, *pv, *pctx, *pt1, *pmc, *pcb, *pmask;
    cudaGetSymbolAddress((void**)&pq,   g_q);
    cudaGetSymbolAddress((void**)&pk,   g_k);
    cudaGetSymbolAddress((void**)&pv,   g_v);
    cudaGetSymbolAddress((void**)&pctx, g_ctx);
    cudaGetSymbolAddress((void**)&pt1,  g_t1);
    cudaGetSymbolAddress((void**)&pmc,  g_mcomb);
    cudaGetSymbolAddress((void**)&pcb,  g_cbias);
    cudaGetSymbolAddress((void**)&pmask,g_mask);

    // 1) fold head_sig into inf2
    combine_sig<<<(NH*HID + 255)/256, 256>>>(head_sig, inf2_w, inf2_b, pmc, pcb);

    // 2) mask MLP (exact fp32 for top-k stability)
    {
        dim3 g(HID/128, MROWS/128);
        sgemm_relu<<<g, 256>>>(query, inf1_w, inf1_b, pt1, EMB);
    }

    // 3) head scores + top-12 mask
    head_scores<<<MROWS/8, 256>>>(pt1, pmc, pcb, pmask);

    // 4) Q,K,V projections (tf32 mma.sync) -> (B,H,S,D). Q scaled by 0.125
    {
        dim3 g(EMB/128, MROWS/128);
        mgemm_tf32<2><<<g, 256>>>(query, q_w, q_b, pq, EMB, 0.125f);
        mgemm_tf32<2><<<g, 256>>>(query, k_w, k_b, pk, EMB, 1.f);
        mgemm_tf32<2><<<g, 256>>>(query, v_w, v_b, pv, EMB, 1.f);
    }

    // 5) tensor-core flash attention + gating -> ctx (S,B,E)
    {
        const int smem = 17408 * (int)sizeof(uint32_t);   // 69632 B
        cudaFuncSetAttribute(flash_tc,
                             cudaFuncAttributeMaxDynamicSharedMemorySize, smem);
        dim3 g(S_LEN/128, BATCH*NH);
        flash_tc<<<g, 256, smem>>>(pq, pk, pv, pmask, pctx);
    }

    // 6) output projection (tf32 mma.sync)
    {
        dim3 g(EMB/128, MROWS/128);
        mgemm_tf32<0><<<g, 256>>>(pctx, out_w, out_b, out, EMB, 1.f);
    }
    (void)in_sizes; (void)n_in; (void)out_size;
}

// round 5
// speedup vs baseline: 3.3085x; 1.1912x over previous
#include <cuda_runtime.h>
#include <math.h>
#include <stdint.h>

#define S_LEN 2048
#define BATCH 2
#define EMB   1024
#define NH    16
#define HD    64
#define HID   512
#define MROWS (S_LEN*BATCH)   // 4096

// ---------------- scratch (static device globals; no allocation) ----------
__device__ float g_q  [BATCH*NH*S_LEN*HD];   // (B,H,S,D) tf32-rounded
__device__ float g_k  [BATCH*NH*S_LEN*HD];
__device__ float g_v  [BATCH*NH*S_LEN*HD];
__device__ float g_ctx[MROWS*EMB];           // (S,B,E) tf32-rounded
__device__ float g_t1 [MROWS*HID];
__device__ float g_mcomb[NH*HID];
__device__ float g_cbias[NH];
__device__ float g_mask[BATCH*NH*S_LEN];
__device__ float g_qr [MROWS*EMB];           // tf32-rounded query
__device__ float g_wq [EMB*EMB];             // tf32-rounded weights
__device__ float g_wk [EMB*EMB];
__device__ float g_wv [EMB*EMB];
__device__ float g_wo [EMB*EMB];

// =================== helpers ===============================================
__device__ __forceinline__ uint32_t f2tf(float x) {
    uint32_t r; asm("cvt.rna.tf32.f32 %0, %1;" : "=r"(r) : "f"(x)); return r;
}
__device__ __forceinline__ float rtf(float x) { return __uint_as_float(f2tf(x)); }
__device__ __forceinline__ uint32_t smem_u32(const void* p) {
    uint32_t a;
    asm("{ .reg .u64 t; cvta.to.shared.u64 t, %1; cvt.u32.u64 %0, t; }"
        : "=r"(a) : "l"(p));
    return a;
}
__device__ __forceinline__ void cp16(uint32_t saddr, const void* g) {
    asm volatile("cp.async.cg.shared.global [%0], [%1], 16;"
                 :: "r"(saddr), "l"(g) : "memory");
}
__device__ __forceinline__ void mma_tf32(float* d, const uint32_t* a, const uint32_t* b) {
    asm volatile(
        "mma.sync.aligned.m16n8k8.row.col.f32.tf32.tf32.f32 "
        "{%0,%1,%2,%3}, {%4,%5,%6,%7}, {%8,%9}, {%0,%1,%2,%3};"
        : "+f"(d[0]), "+f"(d[1]), "+f"(d[2]), "+f"(d[3])
        : "r"(a[0]), "r"(a[1]), "r"(a[2]), "r"(a[3]), "r"(b[0]), "r"(b[1]));
}

// ---------------- elementwise tf32 rounding (float4) -----------------------
__global__ void round_tf32(const float* __restrict__ src, float* __restrict__ dst,
                           int n4)
{
    const int i = blockIdx.x * blockDim.x + threadIdx.x;
    if (i < n4) {
        float4 v = ((const float4*)src)[i];
        v.x = rtf(v.x); v.y = rtf(v.y); v.z = rtf(v.z); v.w = rtf(v.w);
        ((float4*)dst)[i] = v;
    }
}

// =================== cp.async pipelined tf32 GEMM ==========================
// Inputs MUST be tf32-pre-rounded. C = (A @ W^T + bias)*scale.
// 128x128 CTA tile, K chunks of 32, 2-stage cp.async double buffer.
// MODE 0: row-major out (fp32). MODE 2: scatter to (B,H,S,D), tf32-rounded.
// smem words: A0@0, W0@4608, A1@9216, W1@13824 (73728 B total)
template<int MODE>
__global__ __launch_bounds__(256, 2)
void mgemm_cp(const float* __restrict__ A, const float* __restrict__ W,
              const float* __restrict__ bias, float* __restrict__ C,
              int K, float scale)
{
    extern __shared__ uint32_t sw[];
    const uint32_t sbase = smem_u32(sw);
    const int tid  = threadIdx.x;
    const int wid  = tid >> 5;
    const int lane = tid & 31;
    const int gid  = lane >> 2;
    const int tig  = lane & 3;
    const int wm   = wid >> 2;
    const int wn   = wid & 3;

    const float* Ag = A + (size_t)blockIdx.y * 128 * K;
    const float* Wg = W + (size_t)blockIdx.x * 128 * K;

    float acc[4][4][4];
    #pragma unroll
    for (int i = 0; i < 4; i++)
        #pragma unroll
        for (int j = 0; j < 4; j++)
            #pragma unroll
            for (int f = 0; f < 4; f++) acc[i][j][f] = 0.f;

    const int NC = K >> 5;
    const int r0 = tid >> 3;            // 0..31 base row (128 rows via 4 iters)
    const int sg = tid & 7;             // 16B segment within 32-float row chunk

    // prologue: chunk 0 -> stage 0
    {
        const uint32_t ab = sbase, wb = sbase + 4608u * 4u;
        #pragma unroll
        for (int i = 0; i < 4; i++) {
            const int row = r0 + i * 32;
            const uint32_t off = (uint32_t)(row * 36 + sg * 4) * 4u;
            cp16(ab + off, Ag + (size_t)row * K + sg * 4);
            cp16(wb + off, Wg + (size_t)row * K + sg * 4);
        }
        asm volatile("cp.async.commit_group;" ::: "memory");
    }

    for (int c = 0; c < NC; c++) {
        if (c + 1 < NC) {
            const uint32_t st = (uint32_t)((c + 1) & 1) * 9216u * 4u;
            const uint32_t ab = sbase + st, wb = sbase + st + 4608u * 4u;
            const int kn = (c + 1) << 5;
            #pragma unroll
            for (int i = 0; i < 4; i++) {
                const int row = r0 + i * 32;
                const uint32_t off = (uint32_t)(row * 36 + sg * 4) * 4u;
                cp16(ab + off, Ag + (size_t)row * K + kn + sg * 4);
                cp16(wb + off, Wg + (size_t)row * K + kn + sg * 4);
            }
            asm volatile("cp.async.commit_group;" ::: "memory");
            asm volatile("cp.async.wait_group 1;" ::: "memory");
        } else {
            asm volatile("cp.async.wait_group 0;" ::: "memory");
        }
        __syncthreads();

        const uint32_t* As = sw + (c & 1) * 9216;
        const uint32_t* Ws = As + 4608;
        #pragma unroll
        for (int ks = 0; ks < 4; ks++) {
            const int k0 = ks * 8;
            uint32_t af[4][4];
            #pragma unroll
            for (int mt = 0; mt < 4; mt++) {
                const int r = wm * 64 + mt * 16 + gid;
                af[mt][0] = As[ r      * 36 + k0 + tig    ];
                af[mt][1] = As[(r + 8) * 36 + k0 + tig    ];
                af[mt][2] = As[ r      * 36 + k0 + tig + 4];
                af[mt][3] = As[(r + 8) * 36 + k0 + tig + 4];
            }
            uint32_t bf[4][2];
            #pragma unroll
            for (int nt = 0; nt < 4; nt++) {
                const int n = wn * 32 + nt * 8 + gid;
                bf[nt][0] = Ws[n * 36 + k0 + tig    ];
                bf[nt][1] = Ws[n * 36 + k0 + tig + 4];
            }
            #pragma unroll
            for (int mt = 0; mt < 4; mt++)
                #pragma unroll
                for (int nt = 0; nt < 4; nt++)
                    mma_tf32(acc[mt][nt], af[mt], bf[nt]);
        }
        __syncthreads();
    }

    #pragma unroll
    for (int mt = 0; mt < 4; mt++) {
        #pragma unroll
        for (int nt = 0; nt < 4; nt++) {
            const int n = blockIdx.x * 128 + wn * 32 + nt * 8 + tig * 2;
            const float b0 = bias[n], b1 = bias[n + 1];
            #pragma unroll
            for (int half = 0; half < 2; half++) {
                const int m = blockIdx.y * 128 + wm * 64 + mt * 16 + gid + half * 8;
                float2 v;
                v.x = (acc[mt][nt][half * 2 + 0] + b0) * scale;
                v.y = (acc[mt][nt][half * 2 + 1] + b1) * scale;
                if (MODE == 2) {
                    v.x = rtf(v.x); v.y = rtf(v.y);   // consumed as tf32 downstream
                    const int s = m >> 1, b = m & 1;
                    const int h = n >> 6, d = n & 63;
                    *(float2*)(C + (((size_t)(b * NH + h)) * S_LEN + s) * HD + d) = v;
                } else {
                    *(float2*)(C + (size_t)m * (gridDim.x * 128) + n) = v;
                }
            }
        }
    }
}

// =================== split-tf32 (3xMMA) GEMM + ReLU for the mask MLP =======
// Near-fp32 accuracy: a = ahi + alo, b = bhi + blo; acc += hi*hi + hi*lo + lo*hi.
// Raw fp32 inputs. Same pipeline as mgemm_cp. Output row-major with ReLU.
__global__ __launch_bounds__(256)
void mgemm_3x_relu(const float* __restrict__ A, const float* __restrict__ W,
                   const float* __restrict__ bias, float* __restrict__ C, int K)
{
    extern __shared__ uint32_t sw[];
    const uint32_t sbase = smem_u32(sw);
    const float* swf = (const float*)sw;
    const int tid  = threadIdx.x;
    const int wid  = tid >> 5;
    const int lane = tid & 31;
    const int gid  = lane >> 2;
    const int tig  = lane & 3;
    const int wm   = wid >> 2;
    const int wn   = wid & 3;

    const float* Ag = A + (size_t)blockIdx.y * 128 * K;
    const float* Wg = W + (size_t)blockIdx.x * 128 * K;

    float acc[4][4][4];
    #pragma unroll
    for (int i = 0; i < 4; i++)
        #pragma unroll
        for (int j = 0; j < 4; j++)
            #pragma unroll
            for (int f = 0; f < 4; f++) acc[i][j][f] = 0.f;

    const int NC = K >> 5;
    const int r0 = tid >> 3;
    const int sg = tid & 7;

    {
        const uint32_t ab = sbase, wb = sbase + 4608u * 4u;
        #pragma unroll
        for (int i = 0; i < 4; i++) {
            const int row = r0 + i * 32;
            const uint32_t off = (uint32_t)(row * 36 + sg * 4) * 4u;
            cp16(ab + off, Ag + (size_t)row * K + sg * 4);
            cp16(wb + off, Wg + (size_t)row * K + sg * 4);
        }
        asm volatile("cp.async.commit_group;" ::: "memory");
    }

    for (int c = 0; c < NC; c++) {
        if (c + 1 < NC) {
            const uint32_t st = (uint32_t)((c + 1) & 1) * 9216u * 4u;
            const uint32_t ab = sbase + st, wb = sbase + st + 4608u * 4u;
            const int kn = (c + 1) << 5;
            #pragma unroll
            for (int i = 0; i < 4; i++) {
                const int row = r0 + i * 32;
                const uint32_t off = (uint32_t)(row * 36 + sg * 4) * 4u;
                cp16(ab + off, Ag + (size_t)row * K + kn + sg * 4);
                cp16(wb + off, Wg + (size_t)row * K + kn + sg * 4);
            }
            asm volatile("cp.async.commit_group;" ::: "memory");
            asm volatile("cp.async.wait_group 1;" ::: "memory");
        } else {
            asm volatile("cp.async.wait_group 0;" ::: "memory");
        }
        __syncthreads();

        const float* As = swf + (c & 1) * 9216;
        const float* Ws = As + 4608;
        #pragma unroll
        for (int ks = 0; ks < 4; ks++) {
            const int k0 = ks * 8;
            uint32_t ah[4][4], al[4][4];
            #pragma unroll
            for (int mt = 0; mt < 4; mt++) {
                const int r = wm * 64 + mt * 16 + gid;
                float a0 = As[ r      * 36 + k0 + tig    ];
                float a1 = As[(r + 8) * 36 + k0 + tig    ];
                float a2 = As[ r      * 36 + k0 + tig + 4];
                float a3 = As[(r + 8) * 36 + k0 + tig + 4];
                ah[mt][0] = f2tf(a0); al[mt][0] = f2tf(a0 - __uint_as_float(ah[mt][0]));
                ah[mt][1] = f2tf(a1); al[mt][1] = f2tf(a1 - __uint_as_float(ah[mt][1]));
                ah[mt][2] = f2tf(a2); al[mt][2] = f2tf(a2 - __uint_as_float(ah[mt][2]));
                ah[mt][3] = f2tf(a3); al[mt][3] = f2tf(a3 - __uint_as_float(ah[mt][3]));
            }
            uint32_t bh_[4][2], bl_[4][2];
            #pragma unroll
            for (int nt = 0; nt < 4; nt++) {
                const int n = wn * 32 + nt * 8 + gid;
                float b0 = Ws[n * 36 + k0 + tig    ];
                float b1 = Ws[n * 36 + k0 + tig + 4];
                bh_[nt][0] = f2tf(b0); bl_[nt][0] = f2tf(b0 - __uint_as_float(bh_[nt][0]));
                bh_[nt][1] = f2tf(b1); bl_[nt][1] = f2tf(b1 - __uint_as_float(bh_[nt][1]));
            }
            #pragma unroll
            for (int mt = 0; mt < 4; mt++)
                #pragma unroll
                for (int nt = 0; nt < 4; nt++) {
                    mma_tf32(acc[mt][nt], al[mt], bh_[nt]);
                    mma_tf32(acc[mt][nt], ah[mt], bl_[nt]);
                    mma_tf32(acc[mt][nt], ah[mt], bh_[nt]);
                }
        }
        __syncthreads();
    }

    #pragma unroll
    for (int mt = 0; mt < 4; mt++) {
        #pragma unroll
        for (int nt = 0; nt < 4; nt++) {
            const int n = blockIdx.x * 128 + wn * 32 + nt * 8 + tig * 2;
            const float b0 = bias[n], b1 = bias[n + 1];
            #pragma unroll
            for (int half = 0; half < 2; half++) {
                const int m = blockIdx.y * 128 + wm * 64 + mt * 16 + gid + half * 8;
                float2 v;
                v.x = fmaxf(acc[mt][nt][half * 2 + 0] + b0, 0.f);
                v.y = fmaxf(acc[mt][nt][half * 2 + 1] + b1, 0.f);
                *(float2*)(C + (size_t)m * (gridDim.x * 128) + n) = v;
            }
        }
    }
}

// =================== tensor-core flash attention ===========================
__global__ __launch_bounds__(256)
void flash_tc(const float* __restrict__ Q, const float* __restrict__ Kg,
              const float* __restrict__ Vg, const float* __restrict__ gate,
              float* __restrict__ ctx)
{
    extern __shared__ uint32_t sw[];
    const uint32_t sbase = smem_u32(sw);
    const int tid  = threadIdx.x;
    const int wid  = tid >> 5;
    const int lane = tid & 31;
    const int gid  = lane >> 2;
    const int tig  = lane & 3;
    const int bh   = blockIdx.y;
    const int b    = bh >> 4, h = bh & 15;
    const int q0   = blockIdx.x * 128;

    const float* Qt = Q  + ((size_t)bh * S_LEN + q0) * HD;
    const float* Kb = Kg + (size_t)bh * S_LEN * HD;
    const float* Vb = Vg + (size_t)bh * S_LEN * HD;

    // ---- stage Q then load Q fragments (inputs already tf32-rounded) ------
    #pragma unroll
    for (int i = 0; i < 8; i++) {
        const int fi = tid + i * 256;
        const int r = fi >> 4, c4 = (fi & 15) * 4;
        float4 v = *(const float4*)(Qt + r * 64 + c4);
        uint32_t* d = &sw[r * 68 + c4];
        d[0] = __float_as_uint(v.x); d[1] = __float_as_uint(v.y);
        d[2] = __float_as_uint(v.z); d[3] = __float_as_uint(v.w);
    }
    __syncthreads();
    uint32_t qa[8][4];
    {
        const int r0 = wid * 16 + gid;
        #pragma unroll
        for (int ks = 0; ks < 8; ks++) {
            qa[ks][0] = sw[ r0      * 68 + ks * 8 + tig    ];
            qa[ks][1] = sw[(r0 + 8) * 68 + ks * 8 + tig    ];
            qa[ks][2] = sw[ r0      * 68 + ks * 8 + tig + 4];
            qa[ks][3] = sw[(r0 + 8) * 68 + ks * 8 + tig + 4];
        }
    }
    __syncthreads();

    #pragma unroll 1
    for (int t = 0; t < 2; t++) {
        const uint32_t kb = sbase + (t ? 8704u : 0u) * 4u;
        const uint32_t vb = kb + 4352u * 4u;
        const float* Ksrc = Kb + (size_t)t * 64 * 64;
        const float* Vsrc = Vb + (size_t)t * 64 * 64;
        #pragma unroll
        for (int i = 0; i < 4; i++) {
            const int fi = tid + i * 256;
            const int r = fi >> 4, c4 = (fi & 15) * 4;
            cp16(kb + (uint32_t)(r * 68 + c4) * 4u, Ksrc + r * 64 + c4);
            cp16(vb + (uint32_t)(r * 68 + c4) * 4u, Vsrc + r * 64 + c4);
        }
        asm volatile("cp.async.commit_group;" ::: "memory");
    }

    float miA = -INFINITY, miB = -INFINITY, liA = 0.f, liB = 0.f;
    float oa[8][4];
    #pragma unroll
    for (int nt = 0; nt < 8; nt++)
        #pragma unroll
        for (int f = 0; f < 4; f++) oa[nt][f] = 0.f;

    const int NT = S_LEN / 64;
    for (int t = 0; t < NT; t++) {
        if (t < NT - 2) asm volatile("cp.async.wait_group 1;" ::: "memory");
        else            asm volatile("cp.async.wait_group 0;" ::: "memory");
        __syncthreads();
        const uint32_t* Ks = sw + ((t & 1) ? 8704 : 0);
        const uint32_t* Vs = Ks + 4352;

        float sa[8][4];
        #pragma unroll
        for (int nt = 0; nt < 8; nt++)
            #pragma unroll
            for (int f = 0; f < 4; f++) sa[nt][f] = 0.f;
        #pragma unroll
        for (int ks = 0; ks < 8; ks++) {
            #pragma unroll
            for (int nt = 0; nt < 8; nt++) {
                uint32_t bf[2];
                bf[0] = Ks[(nt * 8 + gid) * 68 + ks * 8 + tig    ];
                bf[1] = Ks[(nt * 8 + gid) * 68 + ks * 8 + tig + 4];
                mma_tf32(sa[nt], qa[ks], bf);
            }
        }

        float rmA = -INFINITY, rmB = -INFINITY;
        #pragma unroll
        for (int nt = 0; nt < 8; nt++) {
            rmA = fmaxf(rmA, fmaxf(sa[nt][0], sa[nt][1]));
            rmB = fmaxf(rmB, fmaxf(sa[nt][2], sa[nt][3]));
        }
        rmA = fmaxf(rmA, __shfl_xor_sync(0xffffffffu, rmA, 1));
        rmA = fmaxf(rmA, __shfl_xor_sync(0xffffffffu, rmA, 2));
        rmB = fmaxf(rmB, __shfl_xor_sync(0xffffffffu, rmB, 1));
        rmB = fmaxf(rmB, __shfl_xor_sync(0xffffffffu, rmB, 2));

        const float mAn = fmaxf(miA, rmA);
        const float mBn = fmaxf(miB, rmB);
        const float aA  = __expf(miA - mAn);
        const float aB  = __expf(miB - mBn);
        miA = mAn; miB = mBn;

        float rsA = 0.f, rsB = 0.f;
        uint32_t pu[8][4];
        #pragma unroll
        for (int nt = 0; nt < 8; nt++) {
            const float p0 = __expf(sa[nt][0] - mAn);
            const float p1 = __expf(sa[nt][1] - mAn);
            const float p2 = __expf(sa[nt][2] - mBn);
            const float p3 = __expf(sa[nt][3] - mBn);
            rsA += p0 + p1; rsB += p2 + p3;
            pu[nt][0] = f2tf(p0); pu[nt][1] = f2tf(p1);
            pu[nt][2] = f2tf(p2); pu[nt][3] = f2tf(p3);
        }
        rsA += __shfl_xor_sync(0xffffffffu, rsA, 1);
        rsA += __shfl_xor_sync(0xffffffffu, rsA, 2);
        rsB += __shfl_xor_sync(0xffffffffu, rsB, 1);
        rsB += __shfl_xor_sync(0xffffffffu, rsB, 2);
        liA = liA * aA + rsA;
        liB = liB * aB + rsB;
        #pragma unroll
        for (int nt = 0; nt < 8; nt++) {
            oa[nt][0] *= aA; oa[nt][1] *= aA;
            oa[nt][2] *= aB; oa[nt][3] *= aB;
        }

        const int srcA = (lane & ~3) | (tig >> 1);
        const int srcB = srcA + 2;
        #pragma unroll
        for (int ks = 0; ks < 8; ks++) {
            const uint32_t v00 = __shfl_sync(0xffffffffu, pu[ks][0], srcA);
            const uint32_t v01 = __shfl_sync(0xffffffffu, pu[ks][1], srcA);
            const uint32_t v10 = __shfl_sync(0xffffffffu, pu[ks][2], srcA);
            const uint32_t v11 = __shfl_sync(0xffffffffu, pu[ks][3], srcA);
            const uint32_t v20 = __shfl_sync(0xffffffffu, pu[ks][0], srcB);
            const uint32_t v21 = __shfl_sync(0xffffffffu, pu[ks][1], srcB);
            const uint32_t v30 = __shfl_sync(0xffffffffu, pu[ks][2], srcB);
            const uint32_t v31 = __shfl_sync(0xffffffffu, pu[ks][3], srcB);
            uint32_t af[4];
            af[0] = (tig & 1) ? v01 : v00;
            af[1] = (tig & 1) ? v11 : v10;
            af[2] = (tig & 1) ? v21 : v20;
            af[3] = (tig & 1) ? v31 : v30;
            #pragma unroll
            for (int nt = 0; nt < 8; nt++) {
                uint32_t bf[2];
                bf[0] = Vs[(ks * 8 + tig    ) * 68 + nt * 8 + gid];
                bf[1] = Vs[(ks * 8 + tig + 4) * 68 + nt * 8 + gid];
                mma_tf32(oa[nt], af, bf);
            }
        }
        __syncthreads();

        if (t + 2 < NT) {
            const uint32_t kb = sbase + ((t & 1) ? 8704u : 0u) * 4u;
            const uint32_t vb = kb + 4352u * 4u;
            const float* Ksrc = Kb + (size_t)(t + 2) * 64 * 64;
            const float* Vsrc = Vb + (size_t)(t + 2) * 64 * 64;
            #pragma unroll
            for (int i = 0; i < 4; i++) {
                const int fi = tid + i * 256;
                const int r = fi >> 4, c4 = (fi & 15) * 4;
                cp16(kb + (uint32_t)(r * 68 + c4) * 4u, Ksrc + r * 64 + c4);
                cp16(vb + (uint32_t)(r * 68 + c4) * 4u, Vsrc + r * 64 + c4);
            }
            asm volatile("cp.async.commit_group;" ::: "memory");
        }
    }

    const int sA = q0 + wid * 16 + gid;
    const int sB = sA + 8;
    const float gA = gate[(size_t)bh * S_LEN + sA];
    const float gB = gate[(size_t)bh * S_LEN + sB];
    const float invA = gA / liA;
    const float invB = gB / liB;
    #pragma unroll
    for (int nt = 0; nt < 8; nt++) {
        const int col = h * 64 + nt * 8 + tig * 2;
        float2 va = { rtf(oa[nt][0] * invA), rtf(oa[nt][1] * invA) };
        float2 vb = { rtf(oa[nt][2] * invB), rtf(oa[nt][3] * invB) };
        *(float2*)(ctx + ((size_t)sA * BATCH + b) * EMB + col) = va;
        *(float2*)(ctx + ((size_t)sB * BATCH + b) * EMB + col) = vb;
    }
}

// ---------------- fold head_sig into inf2 ---------------------------------
__global__ void combine_sig(const float* __restrict__ hs,
                            const float* __restrict__ w2,
                            const float* __restrict__ b2,
                            float* __restrict__ mcomb,
                            float* __restrict__ cbias)
{
    const int idx = blockIdx.x * blockDim.x + threadIdx.x;
    if (idx < NH * HID) {
        const int h = idx / HID, k = idx % HID;
        float a = 0.f;
        #pragma unroll
        for (int j = 0; j < 64; j++) a += hs[h*64 + j] * w2[j*HID + k];
        mcomb[idx] = a;
    }
    if (idx < NH) {
        float a = 0.f;
        #pragma unroll
        for (int j = 0; j < 64; j++) a += hs[idx*64 + j] * b2[j];
        cbias[idx] = a;
    }
}

// ---------------- per-row head scores + top-12 threshold mask -------------
__global__ __launch_bounds__(256)
void head_scores(const float* __restrict__ t1, const float* __restrict__ mcomb,
                 const float* __restrict__ cbias, float* __restrict__ mask)
{
    const int warp = (blockIdx.x * blockDim.x + threadIdx.x) >> 5;
    const int lane = threadIdx.x & 31;
    if (warp >= MROWS) return;
    const float* row = t1 + (size_t)warp * HID;

    float acc[NH];
    #pragma unroll
    for (int h = 0; h < NH; h++) acc[h] = 0.f;
    for (int k = lane; k < HID; k += 32) {
        const float a = row[k];
        #pragma unroll
        for (int h = 0; h < NH; h++) acc[h] += a * mcomb[h*HID + k];
    }
    #pragma unroll
    for (int h = 0; h < NH; h++)
        #pragma unroll
        for (int off = 16; off > 0; off >>= 1)
            acc[h] += __shfl_xor_sync(0xffffffffu, acc[h], off);

    if (lane == 0) {
        float sc[NH], tmp[NH];
        #pragma unroll
        for (int h = 0; h < NH; h++) { sc[h] = acc[h] + cbias[h]; tmp[h] = sc[h]; }
        float thr = 0.f;
        for (int it = 0; it < NH - 4; it++) {
            int bi = 0; float bv = tmp[0];
            #pragma unroll
            for (int h = 1; h < NH; h++) if (tmp[h] > bv) { bv = tmp[h]; bi = h; }
            thr = bv; tmp[bi] = -INFINITY;
        }
        const int s = warp >> 1, b = warp & 1;
        #pragma unroll
        for (int h = 0; h < NH; h++)
            mask[((size_t)(b * NH + h)) * S_LEN + s] = (sc[h] >= thr) ? 1.f : 0.f;
    }
}

// ---------------------------------------------------------------------------
extern "C" void kernel_launch(void* const* d_in, const int* in_sizes, int n_in,
                              void* d_out, int out_size)
{
    const float* query   = (const float*)d_in[0];
    const float* q_w     = (const float*)d_in[1];
    const float* q_b     = (const float*)d_in[2];
    const float* k_w     = (const float*)d_in[3];
    const float* k_b     = (const float*)d_in[4];
    const float* v_w     = (const float*)d_in[5];
    const float* v_b     = (const float*)d_in[6];
    const float* out_w   = (const float*)d_in[7];
    const float* out_b   = (const float*)d_in[8];
    const float* inf1_w  = (const float*)d_in[9];
    const float* inf1_b  = (const float*)d_in[10];
    const float* inf2_w  = (const float*)d_in[11];
    const float* inf2_b  = (const float*)d_in[12];
    const float* head_sig= (const float*)d_in[13];
    float* out = (float*)d_out;

    float *pq, *pk, *pv, *pctx, *pt1, *pmc, *pcb, *pmask;
    float *pqr, *pwq, *pwk, *pwv, *pwo;
    cudaGetSymbolAddress((void**)&pq,   g_q);
    cudaGetSymbolAddress((void**)&pk,   g_k);
    cudaGetSymbolAddress((void**)&pv,   g_v);
    cudaGetSymbolAddress((void**)&pctx, g_ctx);
    cudaGetSymbolAddress((void**)&pt1,  g_t1);
    cudaGetSymbolAddress((void**)&pmc,  g_mcomb);
    cudaGetSymbolAddress((void**)&pcb,  g_cbias);
    cudaGetSymbolAddress((void**)&pmask,g_mask);
    cudaGetSymbolAddress((void**)&pqr,  g_qr);
    cudaGetSymbolAddress((void**)&pwq,  g_wq);
    cudaGetSymbolAddress((void**)&pwk,  g_wk);
    cudaGetSymbolAddress((void**)&pwv,  g_wv);
    cudaGetSymbolAddress((void**)&pwo,  g_wo);

    const int GS = 73728;   // 2-stage GEMM smem
    cudaFuncSetAttribute(mgemm_cp<0>, cudaFuncAttributeMaxDynamicSharedMemorySize, GS);
    cudaFuncSetAttribute(mgemm_cp<2>, cudaFuncAttributeMaxDynamicSharedMemorySize, GS);
    cudaFuncSetAttribute(mgemm_3x_relu, cudaFuncAttributeMaxDynamicSharedMemorySize, GS);

    // 0) pre-round query + weights to tf32
    {
        const int nq4 = MROWS * EMB / 4, nw4 = EMB * EMB / 4;
        round_tf32<<<(nq4 + 255)/256, 256>>>(query, pqr, nq4);
        round_tf32<<<(nw4 + 255)/256, 256>>>(q_w,  pwq, nw4);
        round_tf32<<<(nw4 + 255)/256, 256>>>(k_w,  pwk, nw4);
        round_tf32<<<(nw4 + 255)/256, 256>>>(v_w,  pwv, nw4);
        round_tf32<<<(nw4 + 255)/256, 256>>>(out_w,pwo, nw4);
    }

    // 1) fold head_sig into inf2
    combine_sig<<<(NH*HID + 255)/256, 256>>>(head_sig, inf2_w, inf2_b, pmc, pcb);

    // 2) mask MLP: split-tf32 (near-fp32) for top-k stability
    {
        dim3 g(HID/128, MROWS/128);
        mgemm_3x_relu<<<g, 256, GS>>>(query, inf1_w, inf1_b, pt1, EMB);
    }

    // 3) head scores + top-12 mask
    head_scores<<<MROWS/8, 256>>>(pt1, pmc, pcb, pmask);

    // 4) Q,K,V projections -> (B,H,S,D). Q scaled by 0.125
    {
        dim3 g(EMB/128, MROWS/128);
        mgemm_cp<2><<<g, 256, GS>>>(pqr, pwq, q_b, pq, EMB, 0.125f);
        mgemm_cp<2><<<g, 256, GS>>>(pqr, pwk, k_b, pk, EMB, 1.f);
        mgemm_cp<2><<<g, 256, GS>>>(pqr, pwv, v_b, pv, EMB, 1.f);
    }

    // 5) tensor-core flash attention + gating -> ctx (S,B,E)
    {
        const int smem = 17408 * (int)sizeof(uint32_t);
        cudaFuncSetAttribute(flash_tc,
                             cudaFuncAttributeMaxDynamicSharedMemorySize, smem);
        dim3 g(S_LEN/128, BATCH*NH);
        flash_tc<<<g, 256, smem>>>(pq, pk, pv, pmask, pctx);
    }

    // 6) output projection
    {
        dim3 g(EMB/128, MROWS/128);
        mgemm_cp<0><<<g, 256, GS>>>(pctx, pwo, out_b, out, EMB, 1.f);
    }
    (void)in_sizes; (void)n_in; (void)out_size;
}

// round 6
// speedup vs baseline: 3.3167x; 1.0025x over previous
#include <cuda_runtime.h>
#include <math.h>
#include <stdint.h>

#define S_LEN 2048
#define BATCH 2
#define EMB   1024
#define NH    16
#define HD    64
#define HID   512
#define MROWS (S_LEN*BATCH)   // 4096
#define HSZ   (BATCH*NH*S_LEN*HD)   // 4M elements per tensor

// ---------------- scratch (static device globals; no allocation) ----------
__device__ float g_qkv[3*HSZ];               // q|k|v in (B,H,S,D), tf32-rounded
__device__ float g_ctx[MROWS*EMB];           // (S,B,E) tf32-rounded
__device__ float g_t1 [MROWS*HID];
__device__ float g_mcomb[NH*HID];
__device__ float g_cbias[NH];
__device__ float g_mask[BATCH*NH*S_LEN];
__device__ float g_qr [MROWS*EMB];           // tf32-rounded query
__device__ float g_wqkv[3*EMB*EMB];          // tf32-rounded q_w|k_w|v_w
__device__ float g_wo [EMB*EMB];             // tf32-rounded out_w

// =================== helpers ===============================================
__device__ __forceinline__ uint32_t f2tf(float x) {
    uint32_t r; asm("cvt.rna.tf32.f32 %0, %1;" : "=r"(r) : "f"(x)); return r;
}
__device__ __forceinline__ float rtf(float x) { return __uint_as_float(f2tf(x)); }
__device__ __forceinline__ uint32_t smem_u32(const void* p) {
    uint32_t a;
    asm("{ .reg .u64 t; cvta.to.shared.u64 t, %1; cvt.u32.u64 %0, t; }"
        : "=r"(a) : "l"(p));
    return a;
}
__device__ __forceinline__ void cp16(uint32_t saddr, const void* g) {
    asm volatile("cp.async.cg.shared.global [%0], [%1], 16;"
                 :: "r"(saddr), "l"(g) : "memory");
}
__device__ __forceinline__ void mma_tf32(float* d, const uint32_t* a, const uint32_t* b) {
    asm volatile(
        "mma.sync.aligned.m16n8k8.row.col.f32.tf32.tf32.f32 "
        "{%0,%1,%2,%3}, {%4,%5,%6,%7}, {%8,%9}, {%0,%1,%2,%3};"
        : "+f"(d[0]), "+f"(d[1]), "+f"(d[2]), "+f"(d[3])
        : "r"(a[0]), "r"(a[1]), "r"(a[2]), "r"(a[3]), "r"(b[0]), "r"(b[1]));
}

// ---------------- fused tf32 rounding of query + 4 weight matrices --------
// seg0: query (1M float4) -> qr ; seg1..3: q_w/k_w/v_w -> wqkv ; seg4: out_w -> wo
#define NQ4 (MROWS*EMB/4)      // 1048576
#define NW4 (EMB*EMB/4)        // 262144 = 1<<18
__global__ void round_all(const float* __restrict__ q,
                          const float* __restrict__ wq,
                          const float* __restrict__ wk,
                          const float* __restrict__ wv,
                          const float* __restrict__ wo,
                          float* __restrict__ dq,
                          float* __restrict__ dwqkv,
                          float* __restrict__ dwo)
{
    const int i = blockIdx.x * blockDim.x + threadIdx.x;
    const float4* src; float4* dst; int off;
    if (i < NQ4) { src = (const float4*)q; dst = (float4*)dq; off = i; }
    else {
        const int j = i - NQ4;
        const int z = j >> 18;
        off = j & (NW4 - 1);
        if      (z == 0) { src = (const float4*)wq; dst = (float4*)dwqkv; }
        else if (z == 1) { src = (const float4*)wk; dst = (float4*)dwqkv + NW4; }
        else if (z == 2) { src = (const float4*)wv; dst = (float4*)dwqkv + 2*NW4; }
        else             { src = (const float4*)wo; dst = (float4*)dwo; }
    }
    float4 v = src[off];
    v.x = rtf(v.x); v.y = rtf(v.y); v.z = rtf(v.z); v.w = rtf(v.w);
    dst[off] = v;
}

// =================== cp.async pipelined tf32 GEMM core =====================
// Computes acc for a 128x128 tile; caller-specific prologue/epilogue wrappers.
#define GEMM_BODY(Ag, Wg)                                                      \
    float acc[4][4][4];                                                        \
    _Pragma("unroll")                                                          \
    for (int i = 0; i < 4; i++)                                                \
        _Pragma("unroll")                                                      \
        for (int j = 0; j < 4; j++)                                            \
            _Pragma("unroll")                                                  \
            for (int f = 0; f < 4; f++) acc[i][j][f] = 0.f;                    \
    const int NC = K >> 5;                                                     \
    const int r0 = tid >> 3;                                                   \
    const int sg = tid & 7;                                                    \
    {                                                                          \
        const uint32_t ab = sbase, wb = sbase + 4608u * 4u;                    \
        _Pragma("unroll")                                                      \
        for (int i = 0; i < 4; i++) {                                          \
            const int row = r0 + i * 32;                                       \
            const uint32_t off = (uint32_t)(row * 36 + sg * 4) * 4u;           \
            cp16(ab + off, Ag + (size_t)row * K + sg * 4);                     \
            cp16(wb + off, Wg + (size_t)row * K + sg * 4);                     \
        }                                                                      \
        asm volatile("cp.async.commit_group;" ::: "memory");                   \
    }                                                                          \
    for (int c = 0; c < NC; c++) {                                             \
        if (c + 1 < NC) {                                                      \
            const uint32_t st = (uint32_t)((c + 1) & 1) * 9216u * 4u;          \
            const uint32_t ab = sbase + st, wb = sbase + st + 4608u * 4u;      \
            const int kn = (c + 1) << 5;                                       \
            _Pragma("unroll")                                                  \
            for (int i = 0; i < 4; i++) {                                      \
                const int row = r0 + i * 32;                                   \
                const uint32_t off = (uint32_t)(row * 36 + sg * 4) * 4u;       \
                cp16(ab + off, Ag + (size_t)row * K + kn + sg * 4);            \
                cp16(wb + off, Wg + (size_t)row * K + kn + sg * 4);            \
            }                                                                  \
            asm volatile("cp.async.commit_group;" ::: "memory");               \
            asm volatile("cp.async.wait_group 1;" ::: "memory");               \
        } else {                                                               \
            asm volatile("cp.async.wait_group 0;" ::: "memory");               \
        }                                                                      \
        __syncthreads();                                                       \
        const uint32_t* As = sw + (c & 1) * 9216;                              \
        const uint32_t* Ws = As + 4608;                                        \
        _Pragma("unroll")                                                      \
        for (int ks = 0; ks < 4; ks++) {                                       \
            const int k0 = ks * 8;                                             \
            uint32_t af[4][4];                                                 \
            _Pragma("unroll")                                                  \
            for (int mt = 0; mt < 4; mt++) {                                   \
                const int r = wm * 64 + mt * 16 + gid;                         \
                af[mt][0] = As[ r      * 36 + k0 + tig    ];                   \
                af[mt][1] = As[(r + 8) * 36 + k0 + tig    ];                   \
                af[mt][2] = As[ r      * 36 + k0 + tig + 4];                   \
                af[mt][3] = As[(r + 8) * 36 + k0 + tig + 4];                   \
            }                                                                  \
            uint32_t bf[4][2];                                                 \
            _Pragma("unroll")                                                  \
            for (int nt = 0; nt < 4; nt++) {                                   \
                const int n = wn * 32 + nt * 8 + gid;                          \
                bf[nt][0] = Ws[n * 36 + k0 + tig    ];                         \
                bf[nt][1] = Ws[n * 36 + k0 + tig + 4];                         \
            }                                                                  \
            _Pragma("unroll")                                                  \
            for (int mt = 0; mt < 4; mt++)                                     \
                _Pragma("unroll")                                              \
                for (int nt = 0; nt < 4; nt++)                                 \
                    mma_tf32(acc[mt][nt], af[mt], bf[nt]);                     \
        }                                                                      \
        __syncthreads();                                                       \
    }

// ---- fused QKV projection: blockIdx.z picks weight/bias/output/scale ------
__global__ __launch_bounds__(256, 2)
void mgemm_qkv(const float* __restrict__ A, const float* __restrict__ Wall,
               const float* __restrict__ bq, const float* __restrict__ bk,
               const float* __restrict__ bv, float* __restrict__ Call, int K)
{
    extern __shared__ uint32_t sw[];
    const uint32_t sbase = smem_u32(sw);
    const int tid  = threadIdx.x;
    const int wid  = tid >> 5;
    const int lane = tid & 31;
    const int gid  = lane >> 2;
    const int tig  = lane & 3;
    const int wm   = wid >> 2;
    const int wn   = wid & 3;
    const int z    = blockIdx.z;

    const float* Ag = A + (size_t)blockIdx.y * 128 * K;
    const float* Wg = Wall + (size_t)z * EMB * EMB + (size_t)blockIdx.x * 128 * K;
    const float* bias = (z == 0) ? bq : (z == 1) ? bk : bv;
    float* C = Call + (size_t)z * HSZ;
    const float scale = (z == 0) ? 0.125f : 1.f;

    GEMM_BODY(Ag, Wg)

    #pragma unroll
    for (int mt = 0; mt < 4; mt++) {
        #pragma unroll
        for (int nt = 0; nt < 4; nt++) {
            const int n = blockIdx.x * 128 + wn * 32 + nt * 8 + tig * 2;
            const float b0 = bias[n], b1 = bias[n + 1];
            #pragma unroll
            for (int half = 0; half < 2; half++) {
                const int m = blockIdx.y * 128 + wm * 64 + mt * 16 + gid + half * 8;
                float2 v;
                v.x = rtf((acc[mt][nt][half * 2 + 0] + b0) * scale);
                v.y = rtf((acc[mt][nt][half * 2 + 1] + b1) * scale);
                const int s = m >> 1, b = m & 1;
                const int h = n >> 6, d = n & 63;
                *(float2*)(C + (((size_t)(b * NH + h)) * S_LEN + s) * HD + d) = v;
            }
        }
    }
}

// ---- output projection: row-major fp32 out --------------------------------
__global__ __launch_bounds__(256, 2)
void mgemm_out(const float* __restrict__ A, const float* __restrict__ W,
               const float* __restrict__ bias, float* __restrict__ C, int K)
{
    extern __shared__ uint32_t sw[];
    const uint32_t sbase = smem_u32(sw);
    const int tid  = threadIdx.x;
    const int wid  = tid >> 5;
    const int lane = tid & 31;
    const int gid  = lane >> 2;
    const int tig  = lane & 3;
    const int wm   = wid >> 2;
    const int wn   = wid & 3;

    const float* Ag = A + (size_t)blockIdx.y * 128 * K;
    const float* Wg = W + (size_t)blockIdx.x * 128 * K;

    GEMM_BODY(Ag, Wg)

    #pragma unroll
    for (int mt = 0; mt < 4; mt++) {
        #pragma unroll
        for (int nt = 0; nt < 4; nt++) {
            const int n = blockIdx.x * 128 + wn * 32 + nt * 8 + tig * 2;
            const float b0 = bias[n], b1 = bias[n + 1];
            #pragma unroll
            for (int half = 0; half < 2; half++) {
                const int m = blockIdx.y * 128 + wm * 64 + mt * 16 + gid + half * 8;
                float2 v;
                v.x = acc[mt][nt][half * 2 + 0] + b0;
                v.y = acc[mt][nt][half * 2 + 1] + b1;
                *(float2*)(C + (size_t)m * (gridDim.x * 128) + n) = v;
            }
        }
    }
}

// =================== split-tf32 (3xMMA) GEMM + ReLU for the mask MLP =======
__global__ __launch_bounds__(256)
void mgemm_3x_relu(const float* __restrict__ A, const float* __restrict__ W,
                   const float* __restrict__ bias, float* __restrict__ C, int K)
{
    extern __shared__ uint32_t sw[];
    const uint32_t sbase = smem_u32(sw);
    const float* swf = (const float*)sw;
    const int tid  = threadIdx.x;
    const int wid  = tid >> 5;
    const int lane = tid & 31;
    const int gid  = lane >> 2;
    const int tig  = lane & 3;
    const int wm   = wid >> 2;
    const int wn   = wid & 3;

    const float* Ag = A + (size_t)blockIdx.y * 128 * K;
    const float* Wg = W + (size_t)blockIdx.x * 128 * K;

    float acc[4][4][4];
    #pragma unroll
    for (int i = 0; i < 4; i++)
        #pragma unroll
        for (int j = 0; j < 4; j++)
            #pragma unroll
            for (int f = 0; f < 4; f++) acc[i][j][f] = 0.f;

    const int NC = K >> 5;
    const int r0 = tid >> 3;
    const int sg = tid & 7;

    {
        const uint32_t ab = sbase, wb = sbase + 4608u * 4u;
        #pragma unroll
        for (int i = 0; i < 4; i++) {
            const int row = r0 + i * 32;
            const uint32_t off = (uint32_t)(row * 36 + sg * 4) * 4u;
            cp16(ab + off, Ag + (size_t)row * K + sg * 4);
            cp16(wb + off, Wg + (size_t)row * K + sg * 4);
        }
        asm volatile("cp.async.commit_group;" ::: "memory");
    }

    for (int c = 0; c < NC; c++) {
        if (c + 1 < NC) {
            const uint32_t st = (uint32_t)((c + 1) & 1) * 9216u * 4u;
            const uint32_t ab = sbase + st, wb = sbase + st + 4608u * 4u;
            const int kn = (c + 1) << 5;
            #pragma unroll
            for (int i = 0; i < 4; i++) {
                const int row = r0 + i * 32;
                const uint32_t off = (uint32_t)(row * 36 + sg * 4) * 4u;
                cp16(ab + off, Ag + (size_t)row * K + kn + sg * 4);
                cp16(wb + off, Wg + (size_t)row * K + kn + sg * 4);
            }
            asm volatile("cp.async.commit_group;" ::: "memory");
            asm volatile("cp.async.wait_group 1;" ::: "memory");
        } else {
            asm volatile("cp.async.wait_group 0;" ::: "memory");
        }
        __syncthreads();

        const float* As = swf + (c & 1) * 9216;
        const float* Ws = As + 4608;
        #pragma unroll
        for (int ks = 0; ks < 4; ks++) {
            const int k0 = ks * 8;
            uint32_t ah[4][4], al[4][4];
            #pragma unroll
            for (int mt = 0; mt < 4; mt++) {
                const int r = wm * 64 + mt * 16 + gid;
                float a0 = As[ r      * 36 + k0 + tig    ];
                float a1 = As[(r + 8) * 36 + k0 + tig    ];
                float a2 = As[ r      * 36 + k0 + tig + 4];
                float a3 = As[(r + 8) * 36 + k0 + tig + 4];
                ah[mt][0] = f2tf(a0); al[mt][0] = f2tf(a0 - __uint_as_float(ah[mt][0]));
                ah[mt][1] = f2tf(a1); al[mt][1] = f2tf(a1 - __uint_as_float(ah[mt][1]));
                ah[mt][2] = f2tf(a2); al[mt][2] = f2tf(a2 - __uint_as_float(ah[mt][2]));
                ah[mt][3] = f2tf(a3); al[mt][3] = f2tf(a3 - __uint_as_float(ah[mt][3]));
            }
            uint32_t bh_[4][2], bl_[4][2];
            #pragma unroll
            for (int nt = 0; nt < 4; nt++) {
                const int n = wn * 32 + nt * 8 + gid;
                float b0 = Ws[n * 36 + k0 + tig    ];
                float b1 = Ws[n * 36 + k0 + tig + 4];
                bh_[nt][0] = f2tf(b0); bl_[nt][0] = f2tf(b0 - __uint_as_float(bh_[nt][0]));
                bh_[nt][1] = f2tf(b1); bl_[nt][1] = f2tf(b1 - __uint_as_float(bh_[nt][1]));
            }
            #pragma unroll
            for (int mt = 0; mt < 4; mt++)
                #pragma unroll
                for (int nt = 0; nt < 4; nt++) {
                    mma_tf32(acc[mt][nt], al[mt], bh_[nt]);
                    mma_tf32(acc[mt][nt], ah[mt], bl_[nt]);
                    mma_tf32(acc[mt][nt], ah[mt], bh_[nt]);
                }
        }
        __syncthreads();
    }

    #pragma unroll
    for (int mt = 0; mt < 4; mt++) {
        #pragma unroll
        for (int nt = 0; nt < 4; nt++) {
            const int n = blockIdx.x * 128 + wn * 32 + nt * 8 + tig * 2;
            const float b0 = bias[n], b1 = bias[n + 1];
            #pragma unroll
            for (int half = 0; half < 2; half++) {
                const int m = blockIdx.y * 128 + wm * 64 + mt * 16 + gid + half * 8;
                float2 v;
                v.x = fmaxf(acc[mt][nt][half * 2 + 0] + b0, 0.f);
                v.y = fmaxf(acc[mt][nt][half * 2 + 1] + b1, 0.f);
                *(float2*)(C + (size_t)m * (gridDim.x * 128) + n) = v;
            }
        }
    }
}

// =================== tensor-core flash attention (3-stage ring) ============
// smem: 3 stages x (K 4352 + V 4352 words) = 26112 words = 104448 B.
// Prefetch for t+2 issued at TOP of iter t (its stage was freed by the
// end-of-iter barrier of t-1), overlapping DMA with compute of t and t+1.
__global__ __launch_bounds__(256)
void flash_tc(const float* __restrict__ Q, const float* __restrict__ Kg,
              const float* __restrict__ Vg, const float* __restrict__ gate,
              float* __restrict__ ctx)
{
    extern __shared__ uint32_t sw[];
    const uint32_t sbase = smem_u32(sw);
    const int tid  = threadIdx.x;
    const int wid  = tid >> 5;
    const int lane = tid & 31;
    const int gid  = lane >> 2;
    const int tig  = lane & 3;
    const int bh   = blockIdx.y;
    const int b    = bh >> 4, h = bh & 15;
    const int q0   = blockIdx.x * 128;

    const float* Qt = Q  + ((size_t)bh * S_LEN + q0) * HD;
    const float* Kb = Kg + (size_t)bh * S_LEN * HD;
    const float* Vb = Vg + (size_t)bh * S_LEN * HD;

    // ---- stage Q then load Q fragments (inputs already tf32-rounded) ------
    #pragma unroll
    for (int i = 0; i < 8; i++) {
        const int fi = tid + i * 256;
        const int r = fi >> 4, c4 = (fi & 15) * 4;
        float4 v = *(const float4*)(Qt + r * 64 + c4);
        uint32_t* d = &sw[r * 68 + c4];
        d[0] = __float_as_uint(v.x); d[1] = __float_as_uint(v.y);
        d[2] = __float_as_uint(v.z); d[3] = __float_as_uint(v.w);
    }
    __syncthreads();
    uint32_t qa[8][4];
    {
        const int r0 = wid * 16 + gid;
        #pragma unroll
        for (int ks = 0; ks < 8; ks++) {
            qa[ks][0] = sw[ r0      * 68 + ks * 8 + tig    ];
            qa[ks][1] = sw[(r0 + 8) * 68 + ks * 8 + tig    ];
            qa[ks][2] = sw[ r0      * 68 + ks * 8 + tig + 4];
            qa[ks][3] = sw[(r0 + 8) * 68 + ks * 8 + tig + 4];
        }
    }
    __syncthreads();

    // ---- issue first two K/V tiles into stages 0,1 -------------------------
    #pragma unroll 1
    for (int t = 0; t < 2; t++) {
        const uint32_t kb = sbase + (uint32_t)t * 8704u * 4u;
        const uint32_t vb = kb + 4352u * 4u;
        const float* Ksrc = Kb + (size_t)t * 64 * 64;
        const float* Vsrc = Vb + (size_t)t * 64 * 64;
        #pragma unroll
        for (int i = 0; i < 4; i++) {
            const int fi = tid + i * 256;
            const int r = fi >> 4, c4 = (fi & 15) * 4;
            cp16(kb + (uint32_t)(r * 68 + c4) * 4u, Ksrc + r * 64 + c4);
            cp16(vb + (uint32_t)(r * 68 + c4) * 4u, Vsrc + r * 64 + c4);
        }
        asm volatile("cp.async.commit_group;" ::: "memory");
    }

    float miA = -INFINITY, miB = -INFINITY, liA = 0.f, liB = 0.f;
    float oa[8][4];
    #pragma unroll
    for (int nt = 0; nt < 8; nt++)
        #pragma unroll
        for (int f = 0; f < 4; f++) oa[nt][f] = 0.f;

    const int NT = S_LEN / 64;
    int stage = 0, pstage = 2;          // consume stage, prefetch stage (mod 3)
    for (int t = 0; t < NT; t++) {
        // prefetch t+2 into pstage (freed by barrier at end of iter t-1)
        if (t + 2 < NT) {
            const uint32_t kb = sbase + (uint32_t)pstage * 8704u * 4u;
            const uint32_t vb = kb + 4352u * 4u;
            const float* Ksrc = Kb + (size_t)(t + 2) * 64 * 64;
            const float* Vsrc = Vb + (size_t)(t + 2) * 64 * 64;
            #pragma unroll
            for (int i = 0; i < 4; i++) {
                const int fi = tid + i * 256;
                const int r = fi >> 4, c4 = (fi & 15) * 4;
                cp16(kb + (uint32_t)(r * 68 + c4) * 4u, Ksrc + r * 64 + c4);
                cp16(vb + (uint32_t)(r * 68 + c4) * 4u, Vsrc + r * 64 + c4);
            }
            asm volatile("cp.async.commit_group;" ::: "memory");
            asm volatile("cp.async.wait_group 2;" ::: "memory");
        } else if (t + 1 < NT) {
            asm volatile("cp.async.wait_group 1;" ::: "memory");
        } else {
            asm volatile("cp.async.wait_group 0;" ::: "memory");
        }
        __syncthreads();
        const uint32_t* Ks = sw + stage * 8704;
        const uint32_t* Vs = Ks + 4352;

        float sa[8][4];
        #pragma unroll
        for (int nt = 0; nt < 8; nt++)
            #pragma unroll
            for (int f = 0; f < 4; f++) sa[nt][f] = 0.f;
        #pragma unroll
        for (int ks = 0; ks < 8; ks++) {
            #pragma unroll
            for (int nt = 0; nt < 8; nt++) {
                uint32_t bf[2];
                bf[0] = Ks[(nt * 8 + gid) * 68 + ks * 8 + tig    ];
                bf[1] = Ks[(nt * 8 + gid) * 68 + ks * 8 + tig + 4];
                mma_tf32(sa[nt], qa[ks], bf);
            }
        }

        float rmA = -INFINITY, rmB = -INFINITY;
        #pragma unroll
        for (int nt = 0; nt < 8; nt++) {
            rmA = fmaxf(rmA, fmaxf(sa[nt][0], sa[nt][1]));
            rmB = fmaxf(rmB, fmaxf(sa[nt][2], sa[nt][3]));
        }
        rmA = fmaxf(rmA, __shfl_xor_sync(0xffffffffu, rmA, 1));
        rmA = fmaxf(rmA, __shfl_xor_sync(0xffffffffu, rmA, 2));
        rmB = fmaxf(rmB, __shfl_xor_sync(0xffffffffu, rmB, 1));
        rmB = fmaxf(rmB, __shfl_xor_sync(0xffffffffu, rmB, 2));

        const float mAn = fmaxf(miA, rmA);
        const float mBn = fmaxf(miB, rmB);
        const float aA  = __expf(miA - mAn);
        const float aB  = __expf(miB - mBn);
        miA = mAn; miB = mBn;

        float rsA = 0.f, rsB = 0.f;
        uint32_t pu[8][4];
        #pragma unroll
        for (int nt = 0; nt < 8; nt++) {
            const float p0 = __expf(sa[nt][0] - mAn);
            const float p1 = __expf(sa[nt][1] - mAn);
            const float p2 = __expf(sa[nt][2] - mBn);
            const float p3 = __expf(sa[nt][3] - mBn);
            rsA += p0 + p1; rsB += p2 + p3;
            pu[nt][0] = f2tf(p0); pu[nt][1] = f2tf(p1);
            pu[nt][2] = f2tf(p2); pu[nt][3] = f2tf(p3);
        }
        rsA += __shfl_xor_sync(0xffffffffu, rsA, 1);
        rsA += __shfl_xor_sync(0xffffffffu, rsA, 2);
        rsB += __shfl_xor_sync(0xffffffffu, rsB, 1);
        rsB += __shfl_xor_sync(0xffffffffu, rsB, 2);
        liA = liA * aA + rsA;
        liB = liB * aB + rsB;
        #pragma unroll
        for (int nt = 0; nt < 8; nt++) {
            oa[nt][0] *= aA; oa[nt][1] *= aA;
            oa[nt][2] *= aB; oa[nt][3] *= aB;
        }

        const int srcA = (lane & ~3) | (tig >> 1);
        const int srcB = srcA + 2;
        #pragma unroll
        for (int ks = 0; ks < 8; ks++) {
            const uint32_t v00 = __shfl_sync(0xffffffffu, pu[ks][0], srcA);
            const uint32_t v01 = __shfl_sync(0xffffffffu, pu[ks][1], srcA);
            const uint32_t v10 = __shfl_sync(0xffffffffu, pu[ks][2], srcA);
            const uint32_t v11 = __shfl_sync(0xffffffffu, pu[ks][3], srcA);
            const uint32_t v20 = __shfl_sync(0xffffffffu, pu[ks][0], srcB);
            const uint32_t v21 = __shfl_sync(0xffffffffu, pu[ks][1], srcB);
            const uint32_t v30 = __shfl_sync(0xffffffffu, pu[ks][2], srcB);
            const uint32_t v31 = __shfl_sync(0xffffffffu, pu[ks][3], srcB);
            uint32_t af[4];
            af[0] = (tig & 1) ? v01 : v00;
            af[1] = (tig & 1) ? v11 : v10;
            af[2] = (tig & 1) ? v21 : v20;
            af[3] = (tig & 1) ? v31 : v30;
            #pragma unroll
            for (int nt = 0; nt < 8; nt++) {
                uint32_t bf[2];
                bf[0] = Vs[(ks * 8 + tig    ) * 68 + nt * 8 + gid];
                bf[1] = Vs[(ks * 8 + tig + 4) * 68 + nt * 8 + gid];
                mma_tf32(oa[nt], af, bf);
            }
        }
        __syncthreads();      // all warps done with 'stage' before it is refilled

        stage  = (stage  == 2) ? 0 : stage  + 1;
        pstage = (pstage == 2) ? 0 : pstage + 1;
    }

    const int sA = q0 + wid * 16 + gid;
    const int sB = sA + 8;
    const float gA = gate[(size_t)bh * S_LEN + sA];
    const float gB = gate[(size_t)bh * S_LEN + sB];
    const float invA = gA / liA;
    const float invB = gB / liB;
    #pragma unroll
    for (int nt = 0; nt < 8; nt++) {
        const int col = h * 64 + nt * 8 + tig * 2;
        float2 va = { rtf(oa[nt][0] * invA), rtf(oa[nt][1] * invA) };
        float2 vb = { rtf(oa[nt][2] * invB), rtf(oa[nt][3] * invB) };
        *(float2*)(ctx + ((size_t)sA * BATCH + b) * EMB + col) = va;
        *(float2*)(ctx + ((size_t)sB * BATCH + b) * EMB + col) = vb;
    }
}

// ---------------- fold head_sig into inf2 ---------------------------------
__global__ void combine_sig(const float* __restrict__ hs,
                            const float* __restrict__ w2,
                            const float* __restrict__ b2,
                            float* __restrict__ mcomb,
                            float* __restrict__ cbias)
{
    const int idx = blockIdx.x * blockDim.x + threadIdx.x;
    if (idx < NH * HID) {
        const int h = idx / HID, k = idx % HID;
        float a = 0.f;
        #pragma unroll
        for (int j = 0; j < 64; j++) a += hs[h*64 + j] * w2[j*HID + k];
        mcomb[idx] = a;
    }
    if (idx < NH) {
        float a = 0.f;
        #pragma unroll
        for (int j = 0; j < 64; j++) a += hs[idx*64 + j] * b2[j];
        cbias[idx] = a;
    }
}

// ---------------- per-row head scores + top-12 threshold mask -------------
__global__ __launch_bounds__(256)
void head_scores(const float* __restrict__ t1, const float* __restrict__ mcomb,
                 const float* __restrict__ cbias, float* __restrict__ mask)
{
    const int warp = (blockIdx.x * blockDim.x + threadIdx.x) >> 5;
    const int lane = threadIdx.x & 31;
    if (warp >= MROWS) return;
    const float* row = t1 + (size_t)warp * HID;

    float acc[NH];
    #pragma unroll
    for (int h = 0; h < NH; h++) acc[h] = 0.f;
    for (int k = lane; k < HID; k += 32) {
        const float a = row[k];
        #pragma unroll
        for (int h = 0; h < NH; h++) acc[h] += a * mcomb[h*HID + k];
    }
    #pragma unroll
    for (int h = 0; h < NH; h++)
        #pragma unroll
        for (int off = 16; off > 0; off >>= 1)
            acc[h] += __shfl_xor_sync(0xffffffffu, acc[h], off);

    if (lane == 0) {
        float sc[NH], tmp[NH];
        #pragma unroll
        for (int h = 0; h < NH; h++) { sc[h] = acc[h] + cbias[h]; tmp[h] = sc[h]; }
        float thr = 0.f;
        for (int it = 0; it < NH - 4; it++) {
            int bi = 0; float bv = tmp[0];
            #pragma unroll
            for (int h = 1; h < NH; h++) if (tmp[h] > bv) { bv = tmp[h]; bi = h; }
            thr = bv; tmp[bi] = -INFINITY;
        }
        const int s = warp >> 1, b = warp & 1;
        #pragma unroll
        for (int h = 0; h < NH; h++)
            mask[((size_t)(b * NH + h)) * S_LEN + s] = (sc[h] >= thr) ? 1.f : 0.f;
    }
}

// ---------------------------------------------------------------------------
extern "C" void kernel_launch(void* const* d_in, const int* in_sizes, int n_in,
                              void* d_out, int out_size)
{
    const float* query   = (const float*)d_in[0];
    const float* q_w     = (const float*)d_in[1];
    const float* q_b     = (const float*)d_in[2];
    const float* k_w     = (const float*)d_in[3];
    const float* k_b     = (const float*)d_in[4];
    const float* v_w     = (const float*)d_in[5];
    const float* v_b     = (const float*)d_in[6];
    const float* out_w   = (const float*)d_in[7];
    const float* out_b   = (const float*)d_in[8];
    const float* inf1_w  = (const float*)d_in[9];
    const float* inf1_b  = (const float*)d_in[10];
    const float* inf2_w  = (const float*)d_in[11];
    const float* inf2_b  = (const float*)d_in[12];
    const float* head_sig= (const float*)d_in[13];
    float* out = (float*)d_out;

    float *pqkv, *pctx, *pt1, *pmc, *pcb, *pmask, *pqr, *pwqkv, *pwo;
    cudaGetSymbolAddress((void**)&pqkv, g_qkv);
    cudaGetSymbolAddress((void**)&pctx, g_ctx);
    cudaGetSymbolAddress((void**)&pt1,  g_t1);
    cudaGetSymbolAddress((void**)&pmc,  g_mcomb);
    cudaGetSymbolAddress((void**)&pcb,  g_cbias);
    cudaGetSymbolAddress((void**)&pmask,g_mask);
    cudaGetSymbolAddress((void**)&pqr,  g_qr);
    cudaGetSymbolAddress((void**)&pwqkv,g_wqkv);
    cudaGetSymbolAddress((void**)&pwo,  g_wo);

    const int GS = 73728;
    cudaFuncSetAttribute(mgemm_qkv, cudaFuncAttributeMaxDynamicSharedMemorySize, GS);
    cudaFuncSetAttribute(mgemm_out, cudaFuncAttributeMaxDynamicSharedMemorySize, GS);
    cudaFuncSetAttribute(mgemm_3x_relu, cudaFuncAttributeMaxDynamicSharedMemorySize, GS);

    // 0) pre-round query + all 4 big weight matrices in ONE launch
    {
        const int total = NQ4 + 4 * NW4;   // 2,097,152 float4s
        round_all<<<(total + 255)/256, 256>>>(query, q_w, k_w, v_w, out_w,
                                              pqr, pwqkv, pwo);
    }

    // 1) fold head_sig into inf2
    combine_sig<<<(NH*HID + 255)/256, 256>>>(head_sig, inf2_w, inf2_b, pmc, pcb);

    // 2) mask MLP: split-tf32 (near-fp32) for top-k stability
    {
        dim3 g(HID/128, MROWS/128);
        mgemm_3x_relu<<<g, 256, GS>>>(query, inf1_w, inf1_b, pt1, EMB);
    }

    // 3) head scores + top-12 mask
    head_scores<<<MROWS/8, 256>>>(pt1, pmc, pcb, pmask);

    // 4) fused Q,K,V projections -> (B,H,S,D), one launch (grid.z = 3)
    {
        dim3 g(EMB/128, MROWS/128, 3);
        mgemm_qkv<<<g, 256, GS>>>(pqr, pwqkv, q_b, k_b, v_b, pqkv, EMB);
    }

    // 5) tensor-core flash attention (3-stage ring) + gating -> ctx
    {
        const int smem = 26112 * (int)sizeof(uint32_t);   // 104448 B
        cudaFuncSetAttribute(flash_tc,
                             cudaFuncAttributeMaxDynamicSharedMemorySize, smem);
        dim3 g(S_LEN/128, BATCH*NH);
        flash_tc<<<g, 256, smem>>>(pqkv, pqkv + HSZ, pqkv + 2*HSZ, pmask, pctx);
    }

    // 6) output projection
    {
        dim3 g(EMB/128, MROWS/128);
        mgemm_out<<<g, 256, GS>>>(pctx, pwo, out_b, out, EMB);
    }
    (void)in_sizes; (void)n_in; (void)out_size;
}